// round 1
// baseline (speedup 1.0000x reference)
#include <cuda_runtime.h>
#include <math.h>

#define NU 50000
#define NI 100000
#define NE 200000
#define NREL 32
#define DIM 64
#define NB 4096
#define EKG 2000000
#define EUI 2000000
#define NNODES 150000   // NU + NI

// ---------------- scratch (static device globals; no allocation) ----------------
__device__ float g_y[NE * DIM];        // entity_emb @ W^T, then reused as x_new
__device__ float g_agg[NE * DIM];      // KG segment sum
__device__ float g_deg[NE];            // KG in-degree
__device__ float g_itemkg[NI * DIM];   // item_kg = x_new[item2entity]
__device__ float g_agg2[NNODES * DIM]; // UI segment sum
__device__ float g_intent[2 * DIM];    // intent_emb (2 x 64)
__device__ float g_gate[NREL * DIM];   // sigmoid(relation_emb)

// vectorized no-return global atomic add (sm_90+)
__device__ __forceinline__ void red_add_v4(float* addr, float4 v) {
    asm volatile("red.global.add.v4.f32 [%0], {%1,%2,%3,%4};"
                 :: "l"(addr), "f"(v.x), "f"(v.y), "f"(v.z), "f"(v.w)
                 : "memory");
}

// ---------------- kernels ----------------

__global__ void zero_bufs_kernel() {
    int idx = blockIdx.x * blockDim.x + threadIdx.x;
    const int n1 = NE * DIM / 4;       // g_agg
    const int n2 = NNODES * DIM / 4;   // g_agg2
    const int n3 = NE / 4;             // g_deg
    float4 z = make_float4(0.f, 0.f, 0.f, 0.f);
    if (idx < n1) reinterpret_cast<float4*>(g_agg)[idx] = z;
    if (idx < n2) reinterpret_cast<float4*>(g_agg2)[idx] = z;
    if (idx < n3) reinterpret_cast<float4*>(g_deg)[idx] = z;
}

__global__ void gate_kernel(const float* __restrict__ rel_emb) {
    int idx = blockIdx.x * blockDim.x + threadIdx.x;
    if (idx < NREL * DIM) {
        float v = rel_emb[idx];
        g_gate[idx] = 1.0f / (1.0f + __expf(-v));
    }
}

// y = x @ W^T   (x: NE x 64, W: 64 x 64 row-major; y[n][o] = sum_k x[n][k]*W[o][k])
__global__ void gemm_xw_kernel(const float* __restrict__ x, const float* __restrict__ W) {
    __shared__ float sW[DIM][DIM + 1];
    __shared__ float sX[64][DIM + 1];
    int tid = threadIdx.x;  // 256 threads
    for (int i = tid; i < DIM * DIM; i += 256) sW[i >> 6][i & 63] = W[i];
    int row0 = blockIdx.x * 64;
    for (int i = tid; i < 64 * DIM; i += 256) {
        int r = i >> 6, c = i & 63;
        int gr = row0 + r;
        sX[r][c] = (gr < NE) ? x[gr * DIM + c] : 0.f;
    }
    __syncthreads();
    int r = tid >> 2;          // 0..63 local row
    int o0 = (tid & 3) * 16;   // output group
    float acc[16];
#pragma unroll
    for (int j = 0; j < 16; j++) acc[j] = 0.f;
#pragma unroll
    for (int k = 0; k < DIM; k++) {
        float xv = sX[r][k];
#pragma unroll
        for (int j = 0; j < 16; j++) acc[j] += xv * sW[o0 + j][k];
    }
    int gr = row0 + r;
    if (gr < NE) {
#pragma unroll
        for (int j = 0; j < 16; j += 4) {
            float4 v = make_float4(acc[j], acc[j + 1], acc[j + 2], acc[j + 3]);
            *reinterpret_cast<float4*>(&g_y[gr * DIM + o0 + j]) = v;
        }
    }
}

// KG edges: agg[dst] += y[src] * gate[rel]; deg[dst] += 1
__global__ void kg_edge_kernel(const int* __restrict__ src, const int* __restrict__ dst,
                               const int* __restrict__ rel) {
    long long tid = (long long)blockIdx.x * blockDim.x + threadIdx.x;
    int e = (int)(tid >> 4);
    int q = (int)(tid & 15);
    if (e >= EKG) return;
    int s = src[e], d = dst[e], r = rel[e];
    float4 v = *reinterpret_cast<const float4*>(&g_y[s * DIM + q * 4]);
    float4 g = *reinterpret_cast<const float4*>(&g_gate[r * DIM + q * 4]);
    float4 m = make_float4(v.x * g.x, v.y * g.y, v.z * g.z, v.w * g.w);
    red_add_v4(&g_agg[d * DIM + q * 4], m);
    if (q == 0) atomicAdd(&g_deg[d], 1.0f);
}

// x_new = l2norm(elu(agg/deg + entity_emb))   -> stored into g_y (reuse)
__global__ void kg_post_kernel(const float* __restrict__ ent) {
    int row = blockIdx.x * (blockDim.x >> 5) + (threadIdx.x >> 5);
    int lane = threadIdx.x & 31;
    if (row >= NE) return;
    float inv = 1.0f / fmaxf(g_deg[row], 1.0f);
    float2 a = *reinterpret_cast<const float2*>(&g_agg[row * DIM + lane * 2]);
    float2 x0 = *reinterpret_cast<const float2*>(&ent[row * DIM + lane * 2]);
    float vx = a.x * inv + x0.x;
    float vy = a.y * inv + x0.y;
    vx = (vx > 0.f) ? vx : expm1f(vx);
    vy = (vy > 0.f) ? vy : expm1f(vy);
    float ss = vx * vx + vy * vy;
#pragma unroll
    for (int o = 16; o; o >>= 1) ss += __shfl_xor_sync(0xffffffffu, ss, o);
    float scale = 1.0f / fmaxf(sqrtf(ss), 1e-12f);
    float2 out = make_float2(vx * scale, vy * scale);
    *reinterpret_cast<float2*>(&g_y[row * DIM + lane * 2]) = out;
}

__global__ void gather_items_kernel(const int* __restrict__ i2e) {
    long long tid = (long long)blockIdx.x * blockDim.x + threadIdx.x;
    int item = (int)(tid >> 4);
    int q = (int)(tid & 15);
    if (item >= NI) return;
    int e = i2e[item];
    float4 v = *reinterpret_cast<const float4*>(&g_y[e * DIM + q * 4]);
    *reinterpret_cast<float4*>(&g_itemkg[item * DIM + q * 4]) = v;
}

// UI edges: agg2[row] += vals * all_emb0[col]  (all_emb0 = [user_emb; item_kg])
__global__ void ui_edge_kernel(const int* __restrict__ urow, const int* __restrict__ ucol,
                               const float* __restrict__ vals,
                               const float* __restrict__ user_emb) {
    long long tid = (long long)blockIdx.x * blockDim.x + threadIdx.x;
    int e = (int)(tid >> 4);
    int q = (int)(tid & 15);
    if (e >= EUI) return;
    int rr = urow[e], cc = ucol[e];
    float w = vals[e];
    const float* srcp = (cc < NU) ? (user_emb + (size_t)cc * DIM)
                                  : (g_itemkg + (size_t)(cc - NU) * DIM);
    float4 v = *reinterpret_cast<const float4*>(srcp + q * 4);
    float4 m = make_float4(w * v.x, w * v.y, w * v.z, w * v.w);
    red_add_v4(&g_agg2[rr * DIM + q * 4], m);
}

// intent_emb = softmax(intent_weights, -1) @ relation_emb   (2 x 64)
__global__ void intent_kernel(const float* __restrict__ iw, const float* __restrict__ rel_emb) {
    __shared__ float sw[2][NREL];
    int t = threadIdx.x;  // 64 threads
    if (t < 2) {
        float m = -1e30f;
        for (int k = 0; k < NREL; k++) m = fmaxf(m, iw[t * NREL + k]);
        float s = 0.f;
        for (int k = 0; k < NREL; k++) { float e = expf(iw[t * NREL + k] - m); sw[t][k] = e; s += e; }
        float inv = 1.0f / s;
        for (int k = 0; k < NREL; k++) sw[t][k] *= inv;
    }
    __syncthreads();
    for (int intent = 0; intent < 2; intent++) {
        float acc = 0.f;
        for (int k = 0; k < NREL; k++) acc += sw[intent][k] * rel_emb[k * DIM + t];
        g_intent[intent * DIM + t] = acc;
    }
}

// one warp per query
__global__ void query_kernel(const int* __restrict__ qu, const int* __restrict__ qi,
                             const int* __restrict__ qn,
                             const float* __restrict__ user_emb,
                             const float* __restrict__ router_w,
                             const float* __restrict__ router_b,
                             float* __restrict__ out) {
    int warp = (blockIdx.x * blockDim.x + threadIdx.x) >> 5;
    int lane = threadIdx.x & 31;
    if (warp >= NB) return;
    int uu = qu[warp], pi = qi[warp], ni = qn[warp];

    float2 ue0 = *reinterpret_cast<const float2*>(&user_emb[uu * DIM + lane * 2]);
    float2 ag = *reinterpret_cast<const float2*>(&g_agg2[uu * DIM + lane * 2]);
    float fux = 0.5f * (ue0.x + ag.x);
    float fuy = 0.5f * (ue0.y + ag.y);

    float2 rw0 = *reinterpret_cast<const float2*>(&router_w[lane * 2]);
    float2 rw1 = *reinterpret_cast<const float2*>(&router_w[DIM + lane * 2]);
    float l0 = fux * rw0.x + fuy * rw0.y;
    float l1 = fux * rw1.x + fuy * rw1.y;
#pragma unroll
    for (int o = 16; o; o >>= 1) {
        l0 += __shfl_xor_sync(0xffffffffu, l0, o);
        l1 += __shfl_xor_sync(0xffffffffu, l1, o);
    }
    l0 += router_b[0];
    l1 += router_b[1];
    float m = fmaxf(l0, l1);
    float e0 = expf(l0 - m), e1 = expf(l1 - m);
    float inv = 1.0f / (e0 + e1);
    float p0 = e0 * inv, p1 = e1 * inv;

    float2 i0 = *reinterpret_cast<const float2*>(&g_intent[lane * 2]);
    float2 i1 = *reinterpret_cast<const float2*>(&g_intent[DIM + lane * 2]);
    float uex = fux + p0 * i0.x + p1 * i1.x;
    float uey = fuy + p0 * i0.y + p1 * i1.y;

    // positive item
    float2 ik = *reinterpret_cast<const float2*>(&g_itemkg[pi * DIM + lane * 2]);
    float2 a2 = *reinterpret_cast<const float2*>(&g_agg2[(NU + pi) * DIM + lane * 2]);
    float iex = 1.5f * ik.x + 0.5f * a2.x;
    float iey = 1.5f * ik.y + 0.5f * a2.y;
    float pos = uex * iex + uey * iey;

    // negative item
    float2 nk = *reinterpret_cast<const float2*>(&g_itemkg[ni * DIM + lane * 2]);
    float2 n2 = *reinterpret_cast<const float2*>(&g_agg2[(NU + ni) * DIM + lane * 2]);
    float nex = 1.5f * nk.x + 0.5f * n2.x;
    float ney = 1.5f * nk.y + 0.5f * n2.y;
    float neg = uex * nex + uey * ney;

#pragma unroll
    for (int o = 16; o; o >>= 1) {
        pos += __shfl_xor_sync(0xffffffffu, pos, o);
        neg += __shfl_xor_sync(0xffffffffu, neg, o);
    }
    if (lane == 0) {
        out[warp] = pos;
        out[NB + warp] = neg;
    }
}

// ---------------- launch ----------------
extern "C" void kernel_launch(void* const* d_in, const int* in_sizes, int n_in,
                              void* d_out, int out_size) {
    const int*   u          = (const int*)d_in[0];
    const int*   it         = (const int*)d_in[1];
    const int*   neg_i      = (const int*)d_in[2];
    const float* user_emb   = (const float*)d_in[3];
    const float* entity_emb = (const float*)d_in[4];
    const float* rel_emb    = (const float*)d_in[5];
    const float* intent_w   = (const float*)d_in[6];
    const float* router_w   = (const float*)d_in[7];
    const float* router_b   = (const float*)d_in[8];
    const float* kg_w       = (const float*)d_in[9];
    const float* ui_vals    = (const float*)d_in[10];
    const int*   item2ent   = (const int*)d_in[11];
    const int*   kg_src     = (const int*)d_in[12];
    const int*   kg_dst     = (const int*)d_in[13];
    const int*   kg_rel     = (const int*)d_in[14];
    const int*   ui_row     = (const int*)d_in[15];
    const int*   ui_col     = (const int*)d_in[16];
    float* out = (float*)d_out;

    {
        int n1 = NE * DIM / 4;  // largest
        zero_bufs_kernel<<<(n1 + 255) / 256, 256>>>();
    }
    gate_kernel<<<(NREL * DIM + 255) / 256, 256>>>(rel_emb);
    gemm_xw_kernel<<<(NE + 63) / 64, 256>>>(entity_emb, kg_w);
    {
        long long t = (long long)EKG * 16;
        kg_edge_kernel<<<(unsigned)((t + 255) / 256), 256>>>(kg_src, kg_dst, kg_rel);
    }
    kg_post_kernel<<<(NE + 7) / 8, 256>>>(entity_emb);
    {
        long long t = (long long)NI * 16;
        gather_items_kernel<<<(unsigned)((t + 255) / 256), 256>>>(item2ent);
    }
    {
        long long t = (long long)EUI * 16;
        ui_edge_kernel<<<(unsigned)((t + 255) / 256), 256>>>(ui_row, ui_col, ui_vals, user_emb);
    }
    intent_kernel<<<1, 64>>>(intent_w, rel_emb);
    query_kernel<<<(NB * 32 + 255) / 256, 256>>>(u, it, neg_i, user_emb, router_w, router_b, out);
}

// round 2
// speedup vs baseline: 1.1759x; 1.1759x over previous
#include <cuda_runtime.h>
#include <math.h>

#define NU 50000
#define NI 100000
#define NE 200000
#define NREL 32
#define DIM 64
#define NB 4096
#define EKG 2000000
#define EUI 2000000
#define EUI_HALF 1000000
#define NNODES 150000   // NU + NI

#define GEMM_BLOCKS ((NE + 63) / 64)           // 3125
#define ZF4_AGG  (NE * DIM / 4)                // 3,200,000
#define ZF4_AGG2 (NNODES * DIM / 4)            // 2,400,000
#define ZF4_DEG  (NE / 4)                      // 50,000
#define ZF4_TOT  (ZF4_AGG + ZF4_AGG2 + ZF4_DEG)
#define ZBLOCKS  ((ZF4_TOT + 2047) / 2048)     // 256 thr x 8 f4
#define INIT_BLOCKS (GEMM_BLOCKS + ZBLOCKS)

// ---------------- scratch (static device globals; no allocation) ----------------
__device__ float g_y[NE * DIM];        // entity_emb @ W^T, then reused as x_new
__device__ float g_agg[NE * DIM];      // KG segment sum
__device__ float g_deg[NE];            // KG in-degree
__device__ float g_agg2[NNODES * DIM]; // UI segment sum
__device__ float g_gate[NREL * DIM];   // sigmoid(relation_emb)

// vectorized no-return global atomic add (sm_90+)
__device__ __forceinline__ void red_add_v4(float* addr, float x, float y, float z, float w) {
    asm volatile("red.global.add.v4.f32 [%0], {%1,%2,%3,%4};"
                 :: "l"(addr), "f"(x), "f"(y), "f"(z), "f"(w)
                 : "memory");
}

// ---------------- K1: fused zero + gate + gemm ----------------
// blocks [0, GEMM_BLOCKS): y = entity_emb @ W^T
// blocks [GEMM_BLOCKS, ...): zero g_agg/g_agg2/g_deg; block GEMM_BLOCKS also writes gate
__global__ void init_kernel(const float* __restrict__ x, const float* __restrict__ W,
                            const float* __restrict__ rel_emb) {
    int b = blockIdx.x;
    int tid = threadIdx.x;  // 256
    if (b < GEMM_BLOCKS) {
        __shared__ float sW[DIM][DIM + 1];
        __shared__ float sX[64][DIM + 1];
        for (int i = tid; i < DIM * DIM; i += 256) sW[i >> 6][i & 63] = W[i];
        int row0 = b * 64;
        for (int i = tid; i < 64 * DIM; i += 256) {
            int r = i >> 6, c = i & 63;
            int gr = row0 + r;
            sX[r][c] = (gr < NE) ? x[gr * DIM + c] : 0.f;
        }
        __syncthreads();
        int r = tid >> 2;
        int o0 = (tid & 3) * 16;
        float acc[16];
#pragma unroll
        for (int j = 0; j < 16; j++) acc[j] = 0.f;
#pragma unroll
        for (int k = 0; k < DIM; k++) {
            float xv = sX[r][k];
#pragma unroll
            for (int j = 0; j < 16; j++) acc[j] += xv * sW[o0 + j][k];
        }
        int gr = row0 + r;
        if (gr < NE) {
#pragma unroll
            for (int j = 0; j < 16; j += 4) {
                float4 v = make_float4(acc[j], acc[j + 1], acc[j + 2], acc[j + 3]);
                *reinterpret_cast<float4*>(&g_y[gr * DIM + o0 + j]) = v;
            }
        }
    } else {
        int zb = b - GEMM_BLOCKS;
        if (zb == 0) {
            // gate = sigmoid(relation_emb), 2048 floats
            for (int i = tid; i < NREL * DIM; i += 256) {
                float v = rel_emb[i];
                g_gate[i] = 1.0f / (1.0f + __expf(-v));
            }
        }
        float4 z = make_float4(0.f, 0.f, 0.f, 0.f);
        int base = zb * 2048 + tid;
#pragma unroll
        for (int j = 0; j < 8; j++) {
            int i = base + j * 256;
            if (i < ZF4_AGG) {
                reinterpret_cast<float4*>(g_agg)[i] = z;
            } else if (i < ZF4_AGG + ZF4_AGG2) {
                reinterpret_cast<float4*>(g_agg2)[i - ZF4_AGG] = z;
            } else if (i < ZF4_TOT) {
                reinterpret_cast<float4*>(g_deg)[i - ZF4_AGG - ZF4_AGG2] = z;
            }
        }
    }
}

// ---------------- K2: KG edges: agg[dst] += y[src]*gate[rel]; deg[dst]++ ----------------
// 8 threads per edge, 2 float4 each
__global__ void kg_edge_kernel(const int* __restrict__ src, const int* __restrict__ dst,
                               const int* __restrict__ rel) {
    int t = blockIdx.x * blockDim.x + threadIdx.x;
    int e = t >> 3;
    int q = t & 7;
    if (e >= EKG) return;
    int s = __ldg(src + e), d = __ldg(dst + e), r = __ldg(rel + e);
    const float4* yp = reinterpret_cast<const float4*>(g_y + (size_t)s * DIM) + q;
    const float4* gp = reinterpret_cast<const float4*>(g_gate + r * DIM) + q;
    float4 v0 = __ldg(yp);
    float4 v1 = __ldg(yp + 8);
    float4 g0 = __ldg(gp);
    float4 g1 = __ldg(gp + 8);
    float* ap = g_agg + (size_t)d * DIM + q * 4;
    red_add_v4(ap,      v0.x * g0.x, v0.y * g0.y, v0.z * g0.z, v0.w * g0.w);
    red_add_v4(ap + 32, v1.x * g1.x, v1.y * g1.y, v1.z * g1.z, v1.w * g1.w);
    if (q == 0) atomicAdd(&g_deg[d], 1.0f);
}

// ---------------- K3: x_new = l2norm(elu(agg/deg + ent)) -> g_y ----------------
__global__ void kg_post_kernel(const float* __restrict__ ent) {
    int row = blockIdx.x * (blockDim.x >> 5) + (threadIdx.x >> 5);
    int lane = threadIdx.x & 31;
    if (row >= NE) return;
    float inv = 1.0f / fmaxf(g_deg[row], 1.0f);
    float2 a = *reinterpret_cast<const float2*>(&g_agg[(size_t)row * DIM + lane * 2]);
    float2 x0 = __ldg(reinterpret_cast<const float2*>(&ent[(size_t)row * DIM + lane * 2]));
    float vx = fmaf(a.x, inv, x0.x);
    float vy = fmaf(a.y, inv, x0.y);
    vx = (vx > 0.f) ? vx : expm1f(vx);
    vy = (vy > 0.f) ? vy : expm1f(vy);
    float ss = vx * vx + vy * vy;
#pragma unroll
    for (int o = 16; o; o >>= 1) ss += __shfl_xor_sync(0xffffffffu, ss, o);
    float scale = 1.0f / fmaxf(sqrtf(ss), 1e-12f);
    float2 out = make_float2(vx * scale, vy * scale);
    *reinterpret_cast<float2*>(&g_y[(size_t)row * DIM + lane * 2]) = out;
}

// ---------------- K4: UI edges: agg2[row] += vals * src_emb[col] ----------------
// src_emb[col] = user_emb[col] if col<NU else x_new[item2ent[col-NU]]
// 8 threads per edge
__global__ void ui_edge_kernel(const int* __restrict__ urow, const int* __restrict__ ucol,
                               const float* __restrict__ vals,
                               const float* __restrict__ user_emb,
                               const int* __restrict__ i2e) {
    int t = blockIdx.x * blockDim.x + threadIdx.x;
    int e = t >> 3;
    int q = t & 7;
    if (e >= EUI) return;
    int rr = __ldg(urow + e), cc = __ldg(ucol + e);
    float w = __ldg(vals + e);
    const float4* sp;
    if (cc < NU) {
        sp = reinterpret_cast<const float4*>(user_emb + (size_t)cc * DIM) + q;
    } else {
        int ent = __ldg(i2e + (cc - NU));
        sp = reinterpret_cast<const float4*>(g_y + (size_t)ent * DIM) + q;
    }
    float4 v0 = __ldg(sp);
    float4 v1 = __ldg(sp + 8);
    float* ap = g_agg2 + (size_t)rr * DIM + q * 4;
    red_add_v4(ap,      w * v0.x, w * v0.y, w * v0.z, w * v0.w);
    red_add_v4(ap + 32, w * v1.x, w * v1.y, w * v1.z, w * v1.w);
}

// ---------------- K5: fused intent + queries (one warp per query) ----------------
__global__ void query_kernel(const int* __restrict__ qu, const int* __restrict__ qi,
                             const int* __restrict__ qn,
                             const float* __restrict__ user_emb,
                             const float* __restrict__ router_w,
                             const float* __restrict__ router_b,
                             const float* __restrict__ iw,
                             const float* __restrict__ rel_emb,
                             const int* __restrict__ i2e,
                             float* __restrict__ out) {
    __shared__ float s_intent[2 * DIM];
    int tid = threadIdx.x;  // 256
    // per-block intent_emb = softmax(intent_weights, -1) @ relation_emb (cheap, L1/L2-hit)
    if (tid < 64) {
        __shared__ float sw[2][NREL];
        if (tid < 2) {
            float m = -1e30f;
#pragma unroll
            for (int k = 0; k < NREL; k++) m = fmaxf(m, __ldg(iw + tid * NREL + k));
            float s = 0.f;
#pragma unroll
            for (int k = 0; k < NREL; k++) {
                float e = __expf(__ldg(iw + tid * NREL + k) - m);
                sw[tid][k] = e; s += e;
            }
            float inv = 1.0f / s;
#pragma unroll
            for (int k = 0; k < NREL; k++) sw[tid][k] *= inv;
        }
        __syncwarp(0xffffffffu);  // tid<2 in warp 0; warps 0/1 both reach here
        // warp-level sync insufficient across warp 0/1; use syncthreads below anyway
    }
    __syncthreads();
    if (tid < 64) {
        // recompute via shared sw written by thread 0/1 (visible after syncthreads)
        // (sw lives in shared; redeclare via extern trick not needed: use static shared)
    }
    // NOTE: sw is block-scoped shared in the if above; hoist properly:
    // (implemented below with s_sw)
    __shared__ float s_sw[2][NREL];
    if (tid < 2) {
        float m = -1e30f;
#pragma unroll
        for (int k = 0; k < NREL; k++) m = fmaxf(m, __ldg(iw + tid * NREL + k));
        float s = 0.f;
#pragma unroll
        for (int k = 0; k < NREL; k++) {
            float e = __expf(__ldg(iw + tid * NREL + k) - m);
            s_sw[tid][k] = e; s += e;
        }
        float inv = 1.0f / s;
#pragma unroll
        for (int k = 0; k < NREL; k++) s_sw[tid][k] *= inv;
    }
    __syncthreads();
    if (tid < 64) {
#pragma unroll
        for (int intent = 0; intent < 2; intent++) {
            float acc = 0.f;
#pragma unroll
            for (int k = 0; k < NREL; k++) acc += s_sw[intent][k] * __ldg(rel_emb + k * DIM + tid);
            s_intent[intent * DIM + tid] = acc;
        }
    }
    __syncthreads();

    int warp = (blockIdx.x * blockDim.x + tid) >> 5;
    int lane = tid & 31;
    if (warp >= NB) return;
    int uu = __ldg(qu + warp), pi = __ldg(qi + warp), ni = __ldg(qn + warp);

    float2 ue0 = __ldg(reinterpret_cast<const float2*>(&user_emb[(size_t)uu * DIM + lane * 2]));
    float2 ag = *reinterpret_cast<const float2*>(&g_agg2[(size_t)uu * DIM + lane * 2]);
    float fux = 0.5f * (ue0.x + ag.x);
    float fuy = 0.5f * (ue0.y + ag.y);

    float2 rw0 = __ldg(reinterpret_cast<const float2*>(&router_w[lane * 2]));
    float2 rw1 = __ldg(reinterpret_cast<const float2*>(&router_w[DIM + lane * 2]));
    float l0 = fux * rw0.x + fuy * rw0.y;
    float l1 = fux * rw1.x + fuy * rw1.y;
#pragma unroll
    for (int o = 16; o; o >>= 1) {
        l0 += __shfl_xor_sync(0xffffffffu, l0, o);
        l1 += __shfl_xor_sync(0xffffffffu, l1, o);
    }
    l0 += __ldg(router_b + 0);
    l1 += __ldg(router_b + 1);
    float m = fmaxf(l0, l1);
    float e0 = __expf(l0 - m), e1 = __expf(l1 - m);
    float inv = 1.0f / (e0 + e1);
    float p0 = e0 * inv, p1 = e1 * inv;

    float2 i0 = *reinterpret_cast<const float2*>(&s_intent[lane * 2]);
    float2 i1 = *reinterpret_cast<const float2*>(&s_intent[DIM + lane * 2]);
    float uex = fux + p0 * i0.x + p1 * i1.x;
    float uey = fuy + p0 * i0.y + p1 * i1.y;

    int pe = __ldg(i2e + pi);
    int ne = __ldg(i2e + ni);
    float2 ik = *reinterpret_cast<const float2*>(&g_y[(size_t)pe * DIM + lane * 2]);
    float2 a2 = *reinterpret_cast<const float2*>(&g_agg2[(size_t)(NU + pi) * DIM + lane * 2]);
    float pos = uex * (1.5f * ik.x + 0.5f * a2.x) + uey * (1.5f * ik.y + 0.5f * a2.y);

    float2 nk = *reinterpret_cast<const float2*>(&g_y[(size_t)ne * DIM + lane * 2]);
    float2 n2 = *reinterpret_cast<const float2*>(&g_agg2[(size_t)(NU + ni) * DIM + lane * 2]);
    float neg = uex * (1.5f * nk.x + 0.5f * n2.x) + uey * (1.5f * nk.y + 0.5f * n2.y);

#pragma unroll
    for (int o = 16; o; o >>= 1) {
        pos += __shfl_xor_sync(0xffffffffu, pos, o);
        neg += __shfl_xor_sync(0xffffffffu, neg, o);
    }
    if (lane == 0) {
        out[warp] = pos;
        out[NB + warp] = neg;
    }
}

// ---------------- launch ----------------
extern "C" void kernel_launch(void* const* d_in, const int* in_sizes, int n_in,
                              void* d_out, int out_size) {
    const int*   u          = (const int*)d_in[0];
    const int*   it         = (const int*)d_in[1];
    const int*   neg_i      = (const int*)d_in[2];
    const float* user_emb   = (const float*)d_in[3];
    const float* entity_emb = (const float*)d_in[4];
    const float* rel_emb    = (const float*)d_in[5];
    const float* intent_w   = (const float*)d_in[6];
    const float* router_w   = (const float*)d_in[7];
    const float* router_b   = (const float*)d_in[8];
    const float* kg_w       = (const float*)d_in[9];
    const float* ui_vals    = (const float*)d_in[10];
    const int*   item2ent   = (const int*)d_in[11];
    const int*   kg_src     = (const int*)d_in[12];
    const int*   kg_dst     = (const int*)d_in[13];
    const int*   kg_rel     = (const int*)d_in[14];
    const int*   ui_row     = (const int*)d_in[15];
    const int*   ui_col     = (const int*)d_in[16];
    float* out = (float*)d_out;

    init_kernel<<<INIT_BLOCKS, 256>>>(entity_emb, kg_w, rel_emb);
    kg_edge_kernel<<<(EKG * 8) / 256, 256>>>(kg_src, kg_dst, kg_rel);
    kg_post_kernel<<<(NE + 7) / 8, 256>>>(entity_emb);
    ui_edge_kernel<<<(EUI * 8) / 256, 256>>>(ui_row, ui_col, ui_vals, user_emb, item2ent);
    query_kernel<<<(NB * 32 + 255) / 256, 256>>>(u, it, neg_i, user_emb, router_w, router_b,
                                                 intent_w, rel_emb, item2ent, out);
}

// round 3
// speedup vs baseline: 1.2401x; 1.0545x over previous
#include <cuda_runtime.h>
#include <math.h>

#define NU 50000
#define NI 100000
#define NE 200000
#define NREL 32
#define DIM 64
#define NB 4096
#define EKG 2000000
#define EUI_HALF 1000000
#define NNODES 150000   // NU + NI

#define GEMM_BLOCKS ((NE + 63) / 64)           // 3125
#define ZF4_AGG  (NE * DIM / 4)                // 3,200,000
#define ZF4_AGG2 (NNODES * DIM / 4)            // 2,400,000
#define ZF4_DEG  (NE / 4)                      // 50,000
#define ZF4_TOT  (ZF4_AGG + ZF4_AGG2 + ZF4_DEG)
#define ZBLOCKS  ((ZF4_TOT + 2047) / 2048)
#define INIT_BLOCKS (GEMM_BLOCKS + ZBLOCKS)

#define KG_BLOCKS  ((EKG * 8) / 256)           // 62500
#define UIH_BLOCKS ((EUI_HALF * 8) / 256)      // 31250

// ---------------- scratch (static device globals; no allocation) ----------------
__device__ float g_y[NE * DIM];        // entity_emb @ W^T
__device__ float g_agg[NE * DIM];      // KG segment sum
__device__ float g_deg[NE];            // KG in-degree
__device__ float g_itemkg[NI * DIM];   // per-item post-processed KG embedding
__device__ float g_agg2[NNODES * DIM]; // UI segment sum
__device__ float g_gate[NREL * DIM];   // sigmoid(relation_emb)

// vectorized no-return global atomic add (sm_90+)
__device__ __forceinline__ void red_add_v4(float* addr, float x, float y, float z, float w) {
    asm volatile("red.global.add.v4.f32 [%0], {%1,%2,%3,%4};"
                 :: "l"(addr), "f"(x), "f"(y), "f"(z), "f"(w)
                 : "memory");
}

// ---------------- K1: fused zero + gate + gemm ----------------
__global__ void init_kernel(const float* __restrict__ x, const float* __restrict__ W,
                            const float* __restrict__ rel_emb) {
    int b = blockIdx.x;
    int tid = threadIdx.x;  // 256
    if (b < GEMM_BLOCKS) {
        __shared__ float sW[DIM][DIM + 1];
        __shared__ float sX[64][DIM + 1];
        for (int i = tid; i < DIM * DIM; i += 256) sW[i >> 6][i & 63] = W[i];
        int row0 = b * 64;
        for (int i = tid; i < 64 * DIM; i += 256) {
            int r = i >> 6, c = i & 63;
            int gr = row0 + r;
            sX[r][c] = (gr < NE) ? x[gr * DIM + c] : 0.f;
        }
        __syncthreads();
        int r = tid >> 2;
        int o0 = (tid & 3) * 16;
        float acc[16];
#pragma unroll
        for (int j = 0; j < 16; j++) acc[j] = 0.f;
#pragma unroll
        for (int k = 0; k < DIM; k++) {
            float xv = sX[r][k];
#pragma unroll
            for (int j = 0; j < 16; j++) acc[j] += xv * sW[o0 + j][k];
        }
        int gr = row0 + r;
        if (gr < NE) {
#pragma unroll
            for (int j = 0; j < 16; j += 4) {
                float4 v = make_float4(acc[j], acc[j + 1], acc[j + 2], acc[j + 3]);
                *reinterpret_cast<float4*>(&g_y[gr * DIM + o0 + j]) = v;
            }
        }
    } else {
        int zb = b - GEMM_BLOCKS;
        if (zb == 0) {
            for (int i = tid; i < NREL * DIM; i += 256) {
                float v = rel_emb[i];
                g_gate[i] = 1.0f / (1.0f + __expf(-v));
            }
        }
        float4 z = make_float4(0.f, 0.f, 0.f, 0.f);
        int base = zb * 2048 + tid;
#pragma unroll
        for (int j = 0; j < 8; j++) {
            int i = base + j * 256;
            if (i < ZF4_AGG) {
                reinterpret_cast<float4*>(g_agg)[i] = z;
            } else if (i < ZF4_AGG + ZF4_AGG2) {
                reinterpret_cast<float4*>(g_agg2)[i - ZF4_AGG] = z;
            } else if (i < ZF4_TOT) {
                reinterpret_cast<float4*>(g_deg)[i - ZF4_AGG - ZF4_AGG2] = z;
            }
        }
    }
}

// ---------------- K2: fused KG edges + UI user-half edges ----------------
// blocks [0, KG_BLOCKS): agg[dst] += y[src]*gate[rel]; deg[dst]++
// blocks [KG_BLOCKS, ...): agg2[row] += vals * user_emb[col]  (second-half UI edges: col < NU)
__global__ void edgeA_kernel(const int* __restrict__ src, const int* __restrict__ dst,
                             const int* __restrict__ rel,
                             const int* __restrict__ urow, const int* __restrict__ ucol,
                             const float* __restrict__ vals,
                             const float* __restrict__ user_emb) {
    int b = blockIdx.x;
    if (b < KG_BLOCKS) {
        int t = b * 256 + threadIdx.x;
        int e = t >> 3;
        int q = t & 7;
        int s = __ldg(src + e), d = __ldg(dst + e), r = __ldg(rel + e);
        const float4* yp = reinterpret_cast<const float4*>(g_y + (size_t)s * DIM) + q;
        const float4* gp = reinterpret_cast<const float4*>(g_gate + r * DIM) + q;
        float4 v0 = __ldg(yp);
        float4 v1 = __ldg(yp + 8);
        float4 g0 = __ldg(gp);
        float4 g1 = __ldg(gp + 8);
        float* ap = g_agg + (size_t)d * DIM + q * 4;
        red_add_v4(ap,      v0.x * g0.x, v0.y * g0.y, v0.z * g0.z, v0.w * g0.w);
        red_add_v4(ap + 32, v1.x * g1.x, v1.y * g1.y, v1.z * g1.z, v1.w * g1.w);
        if (q == 0) atomicAdd(&g_deg[d], 1.0f);
    } else {
        int t = (b - KG_BLOCKS) * 256 + threadIdx.x;
        int e = (t >> 3) + EUI_HALF;   // second half: col is a user
        int q = t & 7;
        int rr = __ldg(urow + e), cc = __ldg(ucol + e);
        float w = __ldg(vals + e);
        const float4* sp = reinterpret_cast<const float4*>(user_emb + (size_t)cc * DIM) + q;
        float4 v0 = __ldg(sp);
        float4 v1 = __ldg(sp + 8);
        float* ap = g_agg2 + (size_t)rr * DIM + q * 4;
        red_add_v4(ap,      w * v0.x, w * v0.y, w * v0.z, w * v0.w);
        red_add_v4(ap + 32, w * v1.x, w * v1.y, w * v1.z, w * v1.w);
    }
}

// ---------------- K3: per-ITEM post: itemkg = l2norm(elu(agg[e]/deg[e] + ent[e])) ----------------
__global__ void item_post_kernel(const float* __restrict__ ent, const int* __restrict__ i2e) {
    int item = blockIdx.x * (blockDim.x >> 5) + (threadIdx.x >> 5);
    int lane = threadIdx.x & 31;
    if (item >= NI) return;
    int e = __ldg(i2e + item);
    float inv = 1.0f / fmaxf(g_deg[e], 1.0f);
    float2 a = *reinterpret_cast<const float2*>(&g_agg[(size_t)e * DIM + lane * 2]);
    float2 x0 = __ldg(reinterpret_cast<const float2*>(&ent[(size_t)e * DIM + lane * 2]));
    float vx = fmaf(a.x, inv, x0.x);
    float vy = fmaf(a.y, inv, x0.y);
    vx = (vx > 0.f) ? vx : expm1f(vx);
    vy = (vy > 0.f) ? vy : expm1f(vy);
    float ss = vx * vx + vy * vy;
#pragma unroll
    for (int o = 16; o; o >>= 1) ss += __shfl_xor_sync(0xffffffffu, ss, o);
    float scale = 1.0f / fmaxf(sqrtf(ss), 1e-12f);
    float2 out = make_float2(vx * scale, vy * scale);
    *reinterpret_cast<float2*>(&g_itemkg[(size_t)item * DIM + lane * 2]) = out;
}

// ---------------- K4: UI item-half edges: agg2[row] += vals * itemkg[col-NU] ----------------
__global__ void edgeB_kernel(const int* __restrict__ urow, const int* __restrict__ ucol,
                             const float* __restrict__ vals) {
    int t = blockIdx.x * 256 + threadIdx.x;
    int e = t >> 3;                 // first half: col is an item
    int q = t & 7;
    int rr = __ldg(urow + e), cc = __ldg(ucol + e);
    float w = __ldg(vals + e);
    const float4* sp = reinterpret_cast<const float4*>(g_itemkg + (size_t)(cc - NU) * DIM) + q;
    float4 v0 = __ldg(sp);
    float4 v1 = __ldg(sp + 8);
    float* ap = g_agg2 + (size_t)rr * DIM + q * 4;
    red_add_v4(ap,      w * v0.x, w * v0.y, w * v0.z, w * v0.w);
    red_add_v4(ap + 32, w * v1.x, w * v1.y, w * v1.z, w * v1.w);
}

// ---------------- K5: fused intent + queries (one warp per query) ----------------
__global__ void query_kernel(const int* __restrict__ qu, const int* __restrict__ qi,
                             const int* __restrict__ qn,
                             const float* __restrict__ user_emb,
                             const float* __restrict__ router_w,
                             const float* __restrict__ router_b,
                             const float* __restrict__ iw,
                             const float* __restrict__ rel_emb,
                             float* __restrict__ out) {
    __shared__ float s_intent[2 * DIM];
    __shared__ float s_sw[2][NREL];
    int tid = threadIdx.x;  // 256
    if (tid < 2) {
        float m = -1e30f;
#pragma unroll
        for (int k = 0; k < NREL; k++) m = fmaxf(m, __ldg(iw + tid * NREL + k));
        float s = 0.f;
#pragma unroll
        for (int k = 0; k < NREL; k++) {
            float e = __expf(__ldg(iw + tid * NREL + k) - m);
            s_sw[tid][k] = e; s += e;
        }
        float inv = 1.0f / s;
#pragma unroll
        for (int k = 0; k < NREL; k++) s_sw[tid][k] *= inv;
    }
    __syncthreads();
    if (tid < 64) {
#pragma unroll
        for (int intent = 0; intent < 2; intent++) {
            float acc = 0.f;
#pragma unroll
            for (int k = 0; k < NREL; k++) acc += s_sw[intent][k] * __ldg(rel_emb + k * DIM + tid);
            s_intent[intent * DIM + tid] = acc;
        }
    }
    __syncthreads();

    int warp = (blockIdx.x * blockDim.x + tid) >> 5;
    int lane = tid & 31;
    if (warp >= NB) return;
    int uu = __ldg(qu + warp), pi = __ldg(qi + warp), ni = __ldg(qn + warp);

    float2 ue0 = __ldg(reinterpret_cast<const float2*>(&user_emb[(size_t)uu * DIM + lane * 2]));
    float2 ag = *reinterpret_cast<const float2*>(&g_agg2[(size_t)uu * DIM + lane * 2]);
    float fux = 0.5f * (ue0.x + ag.x);
    float fuy = 0.5f * (ue0.y + ag.y);

    float2 rw0 = __ldg(reinterpret_cast<const float2*>(&router_w[lane * 2]));
    float2 rw1 = __ldg(reinterpret_cast<const float2*>(&router_w[DIM + lane * 2]));
    float l0 = fux * rw0.x + fuy * rw0.y;
    float l1 = fux * rw1.x + fuy * rw1.y;
#pragma unroll
    for (int o = 16; o; o >>= 1) {
        l0 += __shfl_xor_sync(0xffffffffu, l0, o);
        l1 += __shfl_xor_sync(0xffffffffu, l1, o);
    }
    l0 += __ldg(router_b + 0);
    l1 += __ldg(router_b + 1);
    float m = fmaxf(l0, l1);
    float e0 = __expf(l0 - m), e1 = __expf(l1 - m);
    float inv = 1.0f / (e0 + e1);
    float p0 = e0 * inv, p1 = e1 * inv;

    float2 i0 = *reinterpret_cast<const float2*>(&s_intent[lane * 2]);
    float2 i1 = *reinterpret_cast<const float2*>(&s_intent[DIM + lane * 2]);
    float uex = fux + p0 * i0.x + p1 * i1.x;
    float uey = fuy + p0 * i0.y + p1 * i1.y;

    float2 ik = *reinterpret_cast<const float2*>(&g_itemkg[(size_t)pi * DIM + lane * 2]);
    float2 a2 = *reinterpret_cast<const float2*>(&g_agg2[(size_t)(NU + pi) * DIM + lane * 2]);
    float pos = uex * (1.5f * ik.x + 0.5f * a2.x) + uey * (1.5f * ik.y + 0.5f * a2.y);

    float2 nk = *reinterpret_cast<const float2*>(&g_itemkg[(size_t)ni * DIM + lane * 2]);
    float2 n2 = *reinterpret_cast<const float2*>(&g_agg2[(size_t)(NU + ni) * DIM + lane * 2]);
    float neg = uex * (1.5f * nk.x + 0.5f * n2.x) + uey * (1.5f * nk.y + 0.5f * n2.y);

#pragma unroll
    for (int o = 16; o; o >>= 1) {
        pos += __shfl_xor_sync(0xffffffffu, pos, o);
        neg += __shfl_xor_sync(0xffffffffu, neg, o);
    }
    if (lane == 0) {
        out[warp] = pos;
        out[NB + warp] = neg;
    }
}

// ---------------- launch ----------------
extern "C" void kernel_launch(void* const* d_in, const int* in_sizes, int n_in,
                              void* d_out, int out_size) {
    const int*   u          = (const int*)d_in[0];
    const int*   it         = (const int*)d_in[1];
    const int*   neg_i      = (const int*)d_in[2];
    const float* user_emb   = (const float*)d_in[3];
    const float* entity_emb = (const float*)d_in[4];
    const float* rel_emb    = (const float*)d_in[5];
    const float* intent_w   = (const float*)d_in[6];
    const float* router_w   = (const float*)d_in[7];
    const float* router_b   = (const float*)d_in[8];
    const float* kg_w       = (const float*)d_in[9];
    const float* ui_vals    = (const float*)d_in[10];
    const int*   item2ent   = (const int*)d_in[11];
    const int*   kg_src     = (const int*)d_in[12];
    const int*   kg_dst     = (const int*)d_in[13];
    const int*   kg_rel     = (const int*)d_in[14];
    const int*   ui_row     = (const int*)d_in[15];
    const int*   ui_col     = (const int*)d_in[16];
    float* out = (float*)d_out;

    init_kernel<<<INIT_BLOCKS, 256>>>(entity_emb, kg_w, rel_emb);
    edgeA_kernel<<<KG_BLOCKS + UIH_BLOCKS, 256>>>(kg_src, kg_dst, kg_rel,
                                                  ui_row, ui_col, ui_vals, user_emb);
    item_post_kernel<<<(NI + 7) / 8, 256>>>(entity_emb, item2ent);
    edgeB_kernel<<<UIH_BLOCKS, 256>>>(ui_row, ui_col, ui_vals);
    query_kernel<<<(NB * 32 + 255) / 256, 256>>>(u, it, neg_i, user_emb, router_w, router_b,
                                                 intent_w, rel_emb, out);
}

// round 4
// speedup vs baseline: 1.9531x; 1.5750x over previous
#include <cuda_runtime.h>
#include <math.h>

#define NU 50000
#define NI 100000
#define NE 200000
#define NREL 32
#define DIM 64
#define NB 4096
#define EKG 2000000
#define EUI_HALF 1000000
#define NNODES 150000   // NU + NI

#define GEMM_BLOCKS ((NE + 255) / 256)         // 782 (256 rows per block)
#define ZF4_AGG   (NE * DIM / 4)               // 3,200,000
#define ZF4_AGG2  (NNODES * DIM / 4)           // 2,400,000
#define ZF4_DEG   (NE / 4)                     // 50,000
#define ZF4_FLAGE (NE / 16)                    // 12,500
#define ZF4_FLAGN (NNODES / 16)                // 9,375
#define ZF4_TOT   (ZF4_AGG + ZF4_AGG2 + ZF4_DEG + ZF4_FLAGE + ZF4_FLAGN)
#define ZBLOCKS   ((ZF4_TOT + 2047) / 2048)
#define INIT_BLOCKS (GEMM_BLOCKS + ZBLOCKS)

#define KG_BLOCKS  ((EKG * 8) / 256)           // 62500
#define UIH_BLOCKS ((EUI_HALF * 8) / 256)      // 31250

#define NFLAG_WORK (NI + 3 * NB)

// ---------------- scratch (static device globals; no allocation) ----------------
__device__ float g_y[NE * DIM];            // entity_emb @ W^T
__device__ float g_agg[NE * DIM];          // KG segment sum
__device__ float g_deg[NE];                // KG in-degree
__device__ float g_itemkg[NI * DIM];       // per-item post-processed KG embedding
__device__ float g_agg2[NNODES * DIM];     // UI segment sum
__device__ float g_gate[NREL * DIM];       // sigmoid(relation_emb)
__device__ unsigned char g_flagE[NE];      // entity is referenced by some item
__device__ unsigned char g_flagN[NNODES];  // node row needed by the query batch

// vectorized no-return global atomic add (sm_90+)
__device__ __forceinline__ void red_add_v4(float* addr, float x, float y, float z, float w) {
    asm volatile("red.global.add.v4.f32 [%0], {%1,%2,%3,%4};"
                 :: "l"(addr), "f"(x), "f"(y), "f"(z), "f"(w)
                 : "memory");
}

__device__ __forceinline__ unsigned long long pack2(float a, float b) {
    unsigned long long r;
    asm("mov.b64 %0, {%1, %2};" : "=l"(r) : "f"(a), "f"(b));
    return r;
}
__device__ __forceinline__ void unpack2(unsigned long long v, float& a, float& b) {
    asm("mov.b64 {%0, %1}, %2;" : "=f"(a), "=f"(b) : "l"(v));
}
__device__ __forceinline__ void fma2(unsigned long long& d, unsigned long long a,
                                     unsigned long long b) {
    asm("fma.rn.f32x2 %0, %1, %2, %3;" : "=l"(d) : "l"(a), "l"(b), "l"(d));
}

// ---------------- K1: fused zero + gate + gemm ----------------
// GEMM: thread-per-row, Wt in shared (broadcast LDS.128), packed f32x2 FMA.
__global__ void init_kernel(const float* __restrict__ x, const float* __restrict__ W,
                            const float* __restrict__ rel_emb) {
    int b = blockIdx.x;
    int tid = threadIdx.x;  // 256
    if (b < GEMM_BLOCKS) {
        __shared__ float sWt[DIM][DIM];   // sWt[k][o] = W[o][k]
        for (int idx = tid; idx < DIM * DIM; idx += 256) {
            int o = idx >> 6, k = idx & 63;
            sWt[k][o] = W[idx];
        }
        __syncthreads();
        int row = b * 256 + tid;
        if (row >= NE) return;
        const float4* xp = reinterpret_cast<const float4*>(x + (size_t)row * DIM);
        unsigned long long acc[32];
#pragma unroll
        for (int m = 0; m < 32; m++) acc[m] = 0ull;
#pragma unroll 4
        for (int kc = 0; kc < 16; kc++) {
            float4 xq = __ldg(xp + kc);
#pragma unroll
            for (int j = 0; j < 4; j++) {
                float xv = (j == 0) ? xq.x : (j == 1) ? xq.y : (j == 2) ? xq.z : xq.w;
                unsigned long long xx = pack2(xv, xv);
                const float4* wrow = reinterpret_cast<const float4*>(sWt[kc * 4 + j]);
#pragma unroll
                for (int o4 = 0; o4 < 16; o4++) {
                    float4 w = wrow[o4];
                    fma2(acc[2 * o4],     xx, pack2(w.x, w.y));
                    fma2(acc[2 * o4 + 1], xx, pack2(w.z, w.w));
                }
            }
        }
        float4* yp = reinterpret_cast<float4*>(g_y + (size_t)row * DIM);
#pragma unroll
        for (int j = 0; j < 16; j++) {
            float a0, a1, b0, b1;
            unpack2(acc[2 * j], a0, a1);
            unpack2(acc[2 * j + 1], b0, b1);
            yp[j] = make_float4(a0, a1, b0, b1);
        }
    } else {
        int zb = b - GEMM_BLOCKS;
        if (zb == 0) {
            for (int i = tid; i < NREL * DIM; i += 256) {
                float v = rel_emb[i];
                g_gate[i] = 1.0f / (1.0f + __expf(-v));
            }
        }
        float4 z = make_float4(0.f, 0.f, 0.f, 0.f);
        int base = zb * 2048 + tid;
#pragma unroll
        for (int j = 0; j < 8; j++) {
            int i = base + j * 256;
            if (i < ZF4_AGG) {
                reinterpret_cast<float4*>(g_agg)[i] = z;
            } else if (i < ZF4_AGG + ZF4_AGG2) {
                reinterpret_cast<float4*>(g_agg2)[i - ZF4_AGG] = z;
            } else if (i < ZF4_AGG + ZF4_AGG2 + ZF4_DEG) {
                reinterpret_cast<float4*>(g_deg)[i - ZF4_AGG - ZF4_AGG2] = z;
            } else if (i < ZF4_AGG + ZF4_AGG2 + ZF4_DEG + ZF4_FLAGE) {
                reinterpret_cast<float4*>(g_flagE)[i - ZF4_AGG - ZF4_AGG2 - ZF4_DEG] = z;
            } else if (i < ZF4_TOT) {
                reinterpret_cast<float4*>(g_flagN)[i - ZF4_AGG - ZF4_AGG2 - ZF4_DEG - ZF4_FLAGE] = z;
            }
        }
    }
}

// ---------------- K2: set liveness flags ----------------
__global__ void set_flags_kernel(const int* __restrict__ i2e,
                                 const int* __restrict__ qu,
                                 const int* __restrict__ qi,
                                 const int* __restrict__ qn) {
    int t = blockIdx.x * blockDim.x + threadIdx.x;
    if (t < NI) {
        g_flagE[__ldg(i2e + t)] = 1;
    } else {
        int r = t - NI;
        if (r < NB) g_flagN[__ldg(qu + r)] = 1;
        else if (r < 2 * NB) g_flagN[NU + __ldg(qi + r - NB)] = 1;
        else if (r < 3 * NB) g_flagN[NU + __ldg(qn + r - 2 * NB)] = 1;
    }
}

// ---------------- K3: fused KG edges + UI user-half edges, with liveness skip ----------------
__global__ void edgeA_kernel(const int* __restrict__ src, const int* __restrict__ dst,
                             const int* __restrict__ rel,
                             const int* __restrict__ urow, const int* __restrict__ ucol,
                             const float* __restrict__ vals,
                             const float* __restrict__ user_emb) {
    int b = blockIdx.x;
    if (b < KG_BLOCKS) {
        int t = b * 256 + threadIdx.x;
        int e = t >> 3;
        int q = t & 7;
        int d = __ldg(dst + e);
        if (!g_flagE[d]) return;           // dst entity never read downstream
        int s = __ldg(src + e), r = __ldg(rel + e);
        const float4* yp = reinterpret_cast<const float4*>(g_y + (size_t)s * DIM) + q;
        const float4* gp = reinterpret_cast<const float4*>(g_gate + r * DIM) + q;
        float4 v0 = __ldg(yp);
        float4 v1 = __ldg(yp + 8);
        float4 g0 = __ldg(gp);
        float4 g1 = __ldg(gp + 8);
        float* ap = g_agg + (size_t)d * DIM + q * 4;
        red_add_v4(ap,      v0.x * g0.x, v0.y * g0.y, v0.z * g0.z, v0.w * g0.w);
        red_add_v4(ap + 32, v1.x * g1.x, v1.y * g1.y, v1.z * g1.z, v1.w * g1.w);
        if (q == 0) atomicAdd(&g_deg[d], 1.0f);
    } else {
        int t = (b - KG_BLOCKS) * 256 + threadIdx.x;
        int e = (t >> 3) + EUI_HALF;       // second half: row=item-node, col=user
        int q = t & 7;
        int rr = __ldg(urow + e);
        if (!g_flagN[rr]) return;          // row not in query batch
        int cc = __ldg(ucol + e);
        float w = __ldg(vals + e);
        const float4* sp = reinterpret_cast<const float4*>(user_emb + (size_t)cc * DIM) + q;
        float4 v0 = __ldg(sp);
        float4 v1 = __ldg(sp + 8);
        float* ap = g_agg2 + (size_t)rr * DIM + q * 4;
        red_add_v4(ap,      w * v0.x, w * v0.y, w * v0.z, w * v0.w);
        red_add_v4(ap + 32, w * v1.x, w * v1.y, w * v1.z, w * v1.w);
    }
}

// ---------------- K4: per-ITEM post: itemkg = l2norm(elu(agg[e]/deg[e] + ent[e])) ----------------
__global__ void item_post_kernel(const float* __restrict__ ent, const int* __restrict__ i2e) {
    int item = blockIdx.x * (blockDim.x >> 5) + (threadIdx.x >> 5);
    int lane = threadIdx.x & 31;
    if (item >= NI) return;
    int e = __ldg(i2e + item);
    float inv = 1.0f / fmaxf(g_deg[e], 1.0f);
    float2 a = *reinterpret_cast<const float2*>(&g_agg[(size_t)e * DIM + lane * 2]);
    float2 x0 = __ldg(reinterpret_cast<const float2*>(&ent[(size_t)e * DIM + lane * 2]));
    float vx = fmaf(a.x, inv, x0.x);
    float vy = fmaf(a.y, inv, x0.y);
    vx = (vx > 0.f) ? vx : expm1f(vx);
    vy = (vy > 0.f) ? vy : expm1f(vy);
    float ss = vx * vx + vy * vy;
#pragma unroll
    for (int o = 16; o; o >>= 1) ss += __shfl_xor_sync(0xffffffffu, ss, o);
    float scale = 1.0f / fmaxf(sqrtf(ss), 1e-12f);
    float2 out = make_float2(vx * scale, vy * scale);
    *reinterpret_cast<float2*>(&g_itemkg[(size_t)item * DIM + lane * 2]) = out;
}

// ---------------- K5: UI item-half edges (row=user, col=item), with liveness skip ----------------
__global__ void edgeB_kernel(const int* __restrict__ urow, const int* __restrict__ ucol,
                             const float* __restrict__ vals) {
    int t = blockIdx.x * 256 + threadIdx.x;
    int e = t >> 3;
    int q = t & 7;
    int rr = __ldg(urow + e);
    if (!g_flagN[rr]) return;
    int cc = __ldg(ucol + e);
    float w = __ldg(vals + e);
    const float4* sp = reinterpret_cast<const float4*>(g_itemkg + (size_t)(cc - NU) * DIM) + q;
    float4 v0 = __ldg(sp);
    float4 v1 = __ldg(sp + 8);
    float* ap = g_agg2 + (size_t)rr * DIM + q * 4;
    red_add_v4(ap,      w * v0.x, w * v0.y, w * v0.z, w * v0.w);
    red_add_v4(ap + 32, w * v1.x, w * v1.y, w * v1.z, w * v1.w);
}

// ---------------- K6: fused intent + queries (one warp per query) ----------------
__global__ void query_kernel(const int* __restrict__ qu, const int* __restrict__ qi,
                             const int* __restrict__ qn,
                             const float* __restrict__ user_emb,
                             const float* __restrict__ router_w,
                             const float* __restrict__ router_b,
                             const float* __restrict__ iw,
                             const float* __restrict__ rel_emb,
                             float* __restrict__ out) {
    __shared__ float s_intent[2 * DIM];
    __shared__ float s_sw[2][NREL];
    int tid = threadIdx.x;  // 256
    if (tid < 2) {
        float m = -1e30f;
#pragma unroll
        for (int k = 0; k < NREL; k++) m = fmaxf(m, __ldg(iw + tid * NREL + k));
        float s = 0.f;
#pragma unroll
        for (int k = 0; k < NREL; k++) {
            float e = __expf(__ldg(iw + tid * NREL + k) - m);
            s_sw[tid][k] = e; s += e;
        }
        float inv = 1.0f / s;
#pragma unroll
        for (int k = 0; k < NREL; k++) s_sw[tid][k] *= inv;
    }
    __syncthreads();
    if (tid < 64) {
#pragma unroll
        for (int intent = 0; intent < 2; intent++) {
            float acc = 0.f;
#pragma unroll
            for (int k = 0; k < NREL; k++) acc += s_sw[intent][k] * __ldg(rel_emb + k * DIM + tid);
            s_intent[intent * DIM + tid] = acc;
        }
    }
    __syncthreads();

    int warp = (blockIdx.x * blockDim.x + tid) >> 5;
    int lane = tid & 31;
    if (warp >= NB) return;
    int uu = __ldg(qu + warp), pi = __ldg(qi + warp), ni = __ldg(qn + warp);

    float2 ue0 = __ldg(reinterpret_cast<const float2*>(&user_emb[(size_t)uu * DIM + lane * 2]));
    float2 ag = *reinterpret_cast<const float2*>(&g_agg2[(size_t)uu * DIM + lane * 2]);
    float fux = 0.5f * (ue0.x + ag.x);
    float fuy = 0.5f * (ue0.y + ag.y);

    float2 rw0 = __ldg(reinterpret_cast<const float2*>(&router_w[lane * 2]));
    float2 rw1 = __ldg(reinterpret_cast<const float2*>(&router_w[DIM + lane * 2]));
    float l0 = fux * rw0.x + fuy * rw0.y;
    float l1 = fux * rw1.x + fuy * rw1.y;
#pragma unroll
    for (int o = 16; o; o >>= 1) {
        l0 += __shfl_xor_sync(0xffffffffu, l0, o);
        l1 += __shfl_xor_sync(0xffffffffu, l1, o);
    }
    l0 += __ldg(router_b + 0);
    l1 += __ldg(router_b + 1);
    float m = fmaxf(l0, l1);
    float e0 = __expf(l0 - m), e1 = __expf(l1 - m);
    float inv = 1.0f / (e0 + e1);
    float p0 = e0 * inv, p1 = e1 * inv;

    float2 i0 = *reinterpret_cast<const float2*>(&s_intent[lane * 2]);
    float2 i1 = *reinterpret_cast<const float2*>(&s_intent[DIM + lane * 2]);
    float uex = fux + p0 * i0.x + p1 * i1.x;
    float uey = fuy + p0 * i0.y + p1 * i1.y;

    float2 ik = *reinterpret_cast<const float2*>(&g_itemkg[(size_t)pi * DIM + lane * 2]);
    float2 a2 = *reinterpret_cast<const float2*>(&g_agg2[(size_t)(NU + pi) * DIM + lane * 2]);
    float pos = uex * (1.5f * ik.x + 0.5f * a2.x) + uey * (1.5f * ik.y + 0.5f * a2.y);

    float2 nk = *reinterpret_cast<const float2*>(&g_itemkg[(size_t)ni * DIM + lane * 2]);
    float2 n2 = *reinterpret_cast<const float2*>(&g_agg2[(size_t)(NU + ni) * DIM + lane * 2]);
    float neg = uex * (1.5f * nk.x + 0.5f * n2.x) + uey * (1.5f * nk.y + 0.5f * n2.y);

#pragma unroll
    for (int o = 16; o; o >>= 1) {
        pos += __shfl_xor_sync(0xffffffffu, pos, o);
        neg += __shfl_xor_sync(0xffffffffu, neg, o);
    }
    if (lane == 0) {
        out[warp] = pos;
        out[NB + warp] = neg;
    }
}

// ---------------- launch ----------------
extern "C" void kernel_launch(void* const* d_in, const int* in_sizes, int n_in,
                              void* d_out, int out_size) {
    const int*   u          = (const int*)d_in[0];
    const int*   it         = (const int*)d_in[1];
    const int*   neg_i      = (const int*)d_in[2];
    const float* user_emb   = (const float*)d_in[3];
    const float* entity_emb = (const float*)d_in[4];
    const float* rel_emb    = (const float*)d_in[5];
    const float* intent_w   = (const float*)d_in[6];
    const float* router_w   = (const float*)d_in[7];
    const float* router_b   = (const float*)d_in[8];
    const float* kg_w       = (const float*)d_in[9];
    const float* ui_vals    = (const float*)d_in[10];
    const int*   item2ent   = (const int*)d_in[11];
    const int*   kg_src     = (const int*)d_in[12];
    const int*   kg_dst     = (const int*)d_in[13];
    const int*   kg_rel     = (const int*)d_in[14];
    const int*   ui_row     = (const int*)d_in[15];
    const int*   ui_col     = (const int*)d_in[16];
    float* out = (float*)d_out;

    init_kernel<<<INIT_BLOCKS, 256>>>(entity_emb, kg_w, rel_emb);
    set_flags_kernel<<<(NFLAG_WORK + 255) / 256, 256>>>(item2ent, u, it, neg_i);
    edgeA_kernel<<<KG_BLOCKS + UIH_BLOCKS, 256>>>(kg_src, kg_dst, kg_rel,
                                                  ui_row, ui_col, ui_vals, user_emb);
    item_post_kernel<<<(NI + 7) / 8, 256>>>(entity_emb, item2ent);
    edgeB_kernel<<<UIH_BLOCKS, 256>>>(ui_row, ui_col, ui_vals);
    query_kernel<<<(NB * 32 + 255) / 256, 256>>>(u, it, neg_i, user_emb, router_w, router_b,
                                                 intent_w, rel_emb, out);
}

// round 5
// speedup vs baseline: 2.1831x; 1.1178x over previous
#include <cuda_runtime.h>
#include <math.h>

#define NU 50000
#define NI 100000
#define NE 200000
#define NREL 32
#define DIM 64
#define NB 4096
#define EKG 2000000
#define EUI_HALF 1000000
#define NNODES 150000   // NU + NI

#define GEMM_BLOCKS ((NE + 255) / 256)         // 782
#define ZF4_AGG   (NE * DIM / 4)               // 3,200,000
#define ZF4_AGG2  (NNODES * DIM / 4)           // 2,400,000
#define ZF4_DEG   (NE / 4)                     // 50,000
#define ZF4_TOT   (ZF4_AGG + ZF4_AGG2 + ZF4_DEG)
#define ZBLOCKS   ((ZF4_TOT + 2047) / 2048)    // 2759

#define CKG_BLOCKS ((EKG + 255) / 256)         // 7813
#define CUI_BLOCKS ((EUI_HALF + 255) / 256)    // 3907
#define INIT_BLOCKS (GEMM_BLOCKS + ZBLOCKS + CKG_BLOCKS + 2 * CUI_BLOCKS)

#define EA_KG_BLOCKS 2048
#define EA_UI_BLOCKS 256
#define EB_BLOCKS 512

#define NFLAG_WORK (NI + 3 * NB)

// ---------------- scratch (static device globals; no allocation) ----------------
__device__ float g_y[NE * DIM];            // entity_emb @ W^T
__device__ float g_agg[NE * DIM];          // KG segment sum
__device__ float g_deg[NE];                // KG in-degree
__device__ float g_itemkg[NI * DIM];       // per-item post-processed KG embedding
__device__ float g_agg2[NNODES * DIM];     // UI segment sum
__device__ float g_gate[NREL * DIM];       // sigmoid(relation_emb)
__device__ unsigned char g_flagE[NE];      // entity referenced by some item (persistent; zero-init)
__device__ unsigned char g_flagN[NNODES];  // node row needed by query batch (persistent)

__device__ int g_nKG, g_nUIA, g_nUIB;      // compacted counts (reset each call)
__device__ int   g_ksrc[EKG], g_kdst[EKG], g_krel[EKG];
__device__ int   g_arow[EUI_HALF], g_acol[EUI_HALF];
__device__ float g_aval[EUI_HALF];
__device__ int   g_brow[EUI_HALF], g_bcol[EUI_HALF];
__device__ float g_bval[EUI_HALF];

// vectorized no-return global atomic add (sm_90+)
__device__ __forceinline__ void red_add_v4(float* addr, float x, float y, float z, float w) {
    asm volatile("red.global.add.v4.f32 [%0], {%1,%2,%3,%4};"
                 :: "l"(addr), "f"(x), "f"(y), "f"(z), "f"(w)
                 : "memory");
}

__device__ __forceinline__ unsigned long long pack2(float a, float b) {
    unsigned long long r;
    asm("mov.b64 %0, {%1, %2};" : "=l"(r) : "f"(a), "f"(b));
    return r;
}
__device__ __forceinline__ void unpack2(unsigned long long v, float& a, float& b) {
    asm("mov.b64 {%0, %1}, %2;" : "=f"(a), "=f"(b) : "l"(v));
}
__device__ __forceinline__ void fma2(unsigned long long& d, unsigned long long a,
                                     unsigned long long b) {
    asm("fma.rn.f32x2 %0, %1, %2, %3;" : "=l"(d) : "l"(a), "l"(b), "l"(d));
}

// ---------------- K1: flags (persistent) + counter reset ----------------
__global__ void set_flags_kernel(const int* __restrict__ i2e,
                                 const int* __restrict__ qu,
                                 const int* __restrict__ qi,
                                 const int* __restrict__ qn) {
    int t = blockIdx.x * blockDim.x + threadIdx.x;
    if (t == 0) { g_nKG = 0; g_nUIA = 0; g_nUIB = 0; }
    if (t < NI) {
        g_flagE[__ldg(i2e + t)] = 1;
    } else {
        int r = t - NI;
        if (r < NB) g_flagN[__ldg(qu + r)] = 1;
        else if (r < 2 * NB) g_flagN[NU + __ldg(qi + r - NB)] = 1;
        else if (r < 3 * NB) g_flagN[NU + __ldg(qn + r - 2 * NB)] = 1;
    }
}

// ---------------- K2: fused GEMM + zero + edge compaction ----------------
__global__ void init_kernel(const float* __restrict__ x, const float* __restrict__ W,
                            const float* __restrict__ rel_emb,
                            const int* __restrict__ ksrc, const int* __restrict__ kdst,
                            const int* __restrict__ krel,
                            const int* __restrict__ urow, const int* __restrict__ ucol,
                            const float* __restrict__ uval) {
    int b = blockIdx.x;
    int tid = threadIdx.x;  // 256
    int lane = tid & 31;
    if (b < GEMM_BLOCKS) {
        __shared__ float sWt[DIM][DIM];   // sWt[k][o] = W[o][k]
        for (int idx = tid; idx < DIM * DIM; idx += 256) {
            int o = idx >> 6, k = idx & 63;
            sWt[k][o] = W[idx];
        }
        __syncthreads();
        int row = b * 256 + tid;
        if (row >= NE) return;
        const float4* xp = reinterpret_cast<const float4*>(x + (size_t)row * DIM);
        unsigned long long acc[32];
#pragma unroll
        for (int m = 0; m < 32; m++) acc[m] = 0ull;
#pragma unroll 4
        for (int kc = 0; kc < 16; kc++) {
            float4 xq = __ldg(xp + kc);
#pragma unroll
            for (int j = 0; j < 4; j++) {
                float xv = (j == 0) ? xq.x : (j == 1) ? xq.y : (j == 2) ? xq.z : xq.w;
                unsigned long long xx = pack2(xv, xv);
                const float4* wrow = reinterpret_cast<const float4*>(sWt[kc * 4 + j]);
#pragma unroll
                for (int o4 = 0; o4 < 16; o4++) {
                    float4 w = wrow[o4];
                    fma2(acc[2 * o4],     xx, pack2(w.x, w.y));
                    fma2(acc[2 * o4 + 1], xx, pack2(w.z, w.w));
                }
            }
        }
        float4* yp = reinterpret_cast<float4*>(g_y + (size_t)row * DIM);
#pragma unroll
        for (int j = 0; j < 16; j++) {
            float a0, a1, b0, b1;
            unpack2(acc[2 * j], a0, a1);
            unpack2(acc[2 * j + 1], b0, b1);
            yp[j] = make_float4(a0, a1, b0, b1);
        }
        return;
    }
    b -= GEMM_BLOCKS;
    if (b < ZBLOCKS) {
        if (b == 0) {
            for (int i = tid; i < NREL * DIM; i += 256) {
                float v = rel_emb[i];
                g_gate[i] = 1.0f / (1.0f + __expf(-v));
            }
        }
        float4 z = make_float4(0.f, 0.f, 0.f, 0.f);
        int base = b * 2048 + tid;
#pragma unroll
        for (int j = 0; j < 8; j++) {
            int i = base + j * 256;
            if (i < ZF4_AGG) {
                reinterpret_cast<float4*>(g_agg)[i] = z;
            } else if (i < ZF4_AGG + ZF4_AGG2) {
                reinterpret_cast<float4*>(g_agg2)[i - ZF4_AGG] = z;
            } else if (i < ZF4_TOT) {
                reinterpret_cast<float4*>(g_deg)[i - ZF4_AGG - ZF4_AGG2] = z;
            }
        }
        return;
    }
    b -= ZBLOCKS;
    if (b < CKG_BLOCKS) {
        // compact KG edges whose dst is live
        int e = b * 256 + tid;
        bool live = false;
        int s = 0, d = 0, r = 0;
        if (e < EKG) {
            d = __ldg(kdst + e);
            live = (g_flagE[d] != 0);
            if (live) { s = __ldg(ksrc + e); r = __ldg(krel + e); }
        }
        unsigned m = __ballot_sync(0xffffffffu, live);
        if (!m) return;
        int leader = __ffs(m) - 1;
        int base = 0;
        if (lane == leader) base = atomicAdd(&g_nKG, __popc(m));
        base = __shfl_sync(0xffffffffu, base, leader);
        if (live) {
            int off = base + __popc(m & ((1u << lane) - 1u));
            g_ksrc[off] = s; g_kdst[off] = d; g_krel[off] = r;
        }
        return;
    }
    b -= CKG_BLOCKS;
    {
        // compact UI edges whose row is live.
        // range 0: e in [0, EUI_HALF)           row=user, col=item  -> B list
        // range 1: e in [EUI_HALF, 2*EUI_HALF)  row=item, col=user  -> A list
        int half = (b < CUI_BLOCKS) ? 0 : 1;
        int bb = (half == 0) ? b : b - CUI_BLOCKS;
        int e = bb * 256 + tid + half * EUI_HALF;
        bool live = false;
        int rr = 0, cc = 0;
        float vv = 0.f;
        if (e < (half + 1) * EUI_HALF) {
            rr = __ldg(urow + e);
            live = (g_flagN[rr] != 0);
            if (live) { cc = __ldg(ucol + e); vv = __ldg(uval + e); }
        }
        unsigned m = __ballot_sync(0xffffffffu, live);
        if (!m) return;
        int leader = __ffs(m) - 1;
        int base = 0;
        if (lane == leader) base = atomicAdd(half ? &g_nUIA : &g_nUIB, __popc(m));
        base = __shfl_sync(0xffffffffu, base, leader);
        if (live) {
            int off = base + __popc(m & ((1u << lane) - 1u));
            if (half) { g_arow[off] = rr; g_acol[off] = cc; g_aval[off] = vv; }
            else      { g_brow[off] = rr; g_bcol[off] = cc; g_bval[off] = vv; }
        }
    }
}

// ---------------- K3: compacted KG edges + compacted UI user-gather edges ----------------
__global__ void edgeA_kernel(const float* __restrict__ user_emb) {
    int b = blockIdx.x;
    int tid = threadIdx.x;
    int q = tid & 7;
    if (b < EA_KG_BLOCKS) {
        int n = g_nKG;
        int slot = (b * 256 + tid) >> 3;
        for (; slot < n; slot += (EA_KG_BLOCKS * 256) / 8) {
            int s = g_ksrc[slot], d = g_kdst[slot], r = g_krel[slot];
            const float4* yp = reinterpret_cast<const float4*>(g_y + (size_t)s * DIM) + q;
            const float4* gp = reinterpret_cast<const float4*>(g_gate + r * DIM) + q;
            float4 v0 = __ldg(yp);
            float4 v1 = __ldg(yp + 8);
            float4 g0 = __ldg(gp);
            float4 g1 = __ldg(gp + 8);
            float* ap = g_agg + (size_t)d * DIM + q * 4;
            red_add_v4(ap,      v0.x * g0.x, v0.y * g0.y, v0.z * g0.z, v0.w * g0.w);
            red_add_v4(ap + 32, v1.x * g1.x, v1.y * g1.y, v1.z * g1.z, v1.w * g1.w);
            if (q == 0) atomicAdd(&g_deg[d], 1.0f);
        }
    } else {
        int n = g_nUIA;
        int slot = ((b - EA_KG_BLOCKS) * 256 + tid) >> 3;
        for (; slot < n; slot += (EA_UI_BLOCKS * 256) / 8) {
            int rr = g_arow[slot], cc = g_acol[slot];
            float w = g_aval[slot];
            const float4* sp = reinterpret_cast<const float4*>(user_emb + (size_t)cc * DIM) + q;
            float4 v0 = __ldg(sp);
            float4 v1 = __ldg(sp + 8);
            float* ap = g_agg2 + (size_t)rr * DIM + q * 4;
            red_add_v4(ap,      w * v0.x, w * v0.y, w * v0.z, w * v0.w);
            red_add_v4(ap + 32, w * v1.x, w * v1.y, w * v1.z, w * v1.w);
        }
    }
}

// ---------------- K4: per-ITEM post (16 lanes/row, float4) ----------------
__global__ void item_post_kernel(const float* __restrict__ ent, const int* __restrict__ i2e) {
    int tid = threadIdx.x;
    int lane = tid & 31;
    int half = lane >> 4;            // 0/1: which row within warp
    int l16 = lane & 15;
    int item = blockIdx.x * 16 + (tid >> 5) * 2 + half;
    if (item >= NI) return;
    int e = __ldg(i2e + item);
    float inv = 1.0f / fmaxf(g_deg[e], 1.0f);
    float4 a = *reinterpret_cast<const float4*>(&g_agg[(size_t)e * DIM + l16 * 4]);
    float4 x0 = __ldg(reinterpret_cast<const float4*>(&ent[(size_t)e * DIM + l16 * 4]));
    float vx = fmaf(a.x, inv, x0.x);
    float vy = fmaf(a.y, inv, x0.y);
    float vz = fmaf(a.z, inv, x0.z);
    float vw = fmaf(a.w, inv, x0.w);
    vx = (vx > 0.f) ? vx : (__expf(vx) - 1.f);
    vy = (vy > 0.f) ? vy : (__expf(vy) - 1.f);
    vz = (vz > 0.f) ? vz : (__expf(vz) - 1.f);
    vw = (vw > 0.f) ? vw : (__expf(vw) - 1.f);
    float ss = vx * vx + vy * vy + vz * vz + vw * vw;
#pragma unroll
    for (int o = 8; o; o >>= 1) ss += __shfl_xor_sync(0xffffffffu, ss, o);
    float scale = 1.0f / fmaxf(sqrtf(ss), 1e-12f);
    float4 out = make_float4(vx * scale, vy * scale, vz * scale, vw * scale);
    *reinterpret_cast<float4*>(&g_itemkg[(size_t)item * DIM + l16 * 4]) = out;
}

// ---------------- K5: compacted UI item-gather edges ----------------
__global__ void edgeB_kernel() {
    int tid = threadIdx.x;
    int q = tid & 7;
    int n = g_nUIB;
    int slot = (blockIdx.x * 256 + tid) >> 3;
    for (; slot < n; slot += (EB_BLOCKS * 256) / 8) {
        int rr = g_brow[slot], cc = g_bcol[slot];
        float w = g_bval[slot];
        const float4* sp = reinterpret_cast<const float4*>(g_itemkg + (size_t)(cc - NU) * DIM) + q;
        float4 v0 = __ldg(sp);
        float4 v1 = __ldg(sp + 8);
        float* ap = g_agg2 + (size_t)rr * DIM + q * 4;
        red_add_v4(ap,      w * v0.x, w * v0.y, w * v0.z, w * v0.w);
        red_add_v4(ap + 32, w * v1.x, w * v1.y, w * v1.z, w * v1.w);
    }
}

// ---------------- K6: fused intent + queries (one warp per query) ----------------
__global__ void query_kernel(const int* __restrict__ qu, const int* __restrict__ qi,
                             const int* __restrict__ qn,
                             const float* __restrict__ user_emb,
                             const float* __restrict__ router_w,
                             const float* __restrict__ router_b,
                             const float* __restrict__ iw,
                             const float* __restrict__ rel_emb,
                             float* __restrict__ out) {
    __shared__ float s_intent[2 * DIM];
    __shared__ float s_sw[2][NREL];
    int tid = threadIdx.x;  // 256
    if (tid < 2) {
        float m = -1e30f;
#pragma unroll
        for (int k = 0; k < NREL; k++) m = fmaxf(m, __ldg(iw + tid * NREL + k));
        float s = 0.f;
#pragma unroll
        for (int k = 0; k < NREL; k++) {
            float e = __expf(__ldg(iw + tid * NREL + k) - m);
            s_sw[tid][k] = e; s += e;
        }
        float inv = 1.0f / s;
#pragma unroll
        for (int k = 0; k < NREL; k++) s_sw[tid][k] *= inv;
    }
    __syncthreads();
    if (tid < 64) {
#pragma unroll
        for (int intent = 0; intent < 2; intent++) {
            float acc = 0.f;
#pragma unroll
            for (int k = 0; k < NREL; k++) acc += s_sw[intent][k] * __ldg(rel_emb + k * DIM + tid);
            s_intent[intent * DIM + tid] = acc;
        }
    }
    __syncthreads();

    int warp = (blockIdx.x * blockDim.x + tid) >> 5;
    int lane = tid & 31;
    if (warp >= NB) return;
    int uu = __ldg(qu + warp), pi = __ldg(qi + warp), ni = __ldg(qn + warp);

    float2 ue0 = __ldg(reinterpret_cast<const float2*>(&user_emb[(size_t)uu * DIM + lane * 2]));
    float2 ag = *reinterpret_cast<const float2*>(&g_agg2[(size_t)uu * DIM + lane * 2]);
    float fux = 0.5f * (ue0.x + ag.x);
    float fuy = 0.5f * (ue0.y + ag.y);

    float2 rw0 = __ldg(reinterpret_cast<const float2*>(&router_w[lane * 2]));
    float2 rw1 = __ldg(reinterpret_cast<const float2*>(&router_w[DIM + lane * 2]));
    float l0 = fux * rw0.x + fuy * rw0.y;
    float l1 = fux * rw1.x + fuy * rw1.y;
#pragma unroll
    for (int o = 16; o; o >>= 1) {
        l0 += __shfl_xor_sync(0xffffffffu, l0, o);
        l1 += __shfl_xor_sync(0xffffffffu, l1, o);
    }
    l0 += __ldg(router_b + 0);
    l1 += __ldg(router_b + 1);
    float m = fmaxf(l0, l1);
    float e0 = __expf(l0 - m), e1 = __expf(l1 - m);
    float inv = 1.0f / (e0 + e1);
    float p0 = e0 * inv, p1 = e1 * inv;

    float2 i0 = *reinterpret_cast<const float2*>(&s_intent[lane * 2]);
    float2 i1 = *reinterpret_cast<const float2*>(&s_intent[DIM + lane * 2]);
    float uex = fux + p0 * i0.x + p1 * i1.x;
    float uey = fuy + p0 * i0.y + p1 * i1.y;

    float2 ik = *reinterpret_cast<const float2*>(&g_itemkg[(size_t)pi * DIM + lane * 2]);
    float2 a2 = *reinterpret_cast<const float2*>(&g_agg2[(size_t)(NU + pi) * DIM + lane * 2]);
    float pos = uex * (1.5f * ik.x + 0.5f * a2.x) + uey * (1.5f * ik.y + 0.5f * a2.y);

    float2 nk = *reinterpret_cast<const float2*>(&g_itemkg[(size_t)ni * DIM + lane * 2]);
    float2 n2 = *reinterpret_cast<const float2*>(&g_agg2[(size_t)(NU + ni) * DIM + lane * 2]);
    float neg = uex * (1.5f * nk.x + 0.5f * n2.x) + uey * (1.5f * nk.y + 0.5f * n2.y);

#pragma unroll
    for (int o = 16; o; o >>= 1) {
        pos += __shfl_xor_sync(0xffffffffu, pos, o);
        neg += __shfl_xor_sync(0xffffffffu, neg, o);
    }
    if (lane == 0) {
        out[warp] = pos;
        out[NB + warp] = neg;
    }
}

// ---------------- launch ----------------
extern "C" void kernel_launch(void* const* d_in, const int* in_sizes, int n_in,
                              void* d_out, int out_size) {
    const int*   u          = (const int*)d_in[0];
    const int*   it         = (const int*)d_in[1];
    const int*   neg_i      = (const int*)d_in[2];
    const float* user_emb   = (const float*)d_in[3];
    const float* entity_emb = (const float*)d_in[4];
    const float* rel_emb    = (const float*)d_in[5];
    const float* intent_w   = (const float*)d_in[6];
    const float* router_w   = (const float*)d_in[7];
    const float* router_b   = (const float*)d_in[8];
    const float* kg_w       = (const float*)d_in[9];
    const float* ui_vals    = (const float*)d_in[10];
    const int*   item2ent   = (const int*)d_in[11];
    const int*   kg_src     = (const int*)d_in[12];
    const int*   kg_dst     = (const int*)d_in[13];
    const int*   kg_rel     = (const int*)d_in[14];
    const int*   ui_row     = (const int*)d_in[15];
    const int*   ui_col     = (const int*)d_in[16];
    float* out = (float*)d_out;

    set_flags_kernel<<<(NFLAG_WORK + 255) / 256, 256>>>(item2ent, u, it, neg_i);
    init_kernel<<<INIT_BLOCKS, 256>>>(entity_emb, kg_w, rel_emb,
                                      kg_src, kg_dst, kg_rel,
                                      ui_row, ui_col, ui_vals);
    edgeA_kernel<<<EA_KG_BLOCKS + EA_UI_BLOCKS, 256>>>(user_emb);
    item_post_kernel<<<(NI + 15) / 16, 256>>>(entity_emb, item2ent);
    edgeB_kernel<<<EB_BLOCKS, 256>>>();
    query_kernel<<<(NB * 32 + 255) / 256, 256>>>(u, it, neg_i, user_emb, router_w, router_b,
                                                 intent_w, rel_emb, out);
}

// round 6
// speedup vs baseline: 2.1871x; 1.0018x over previous
#include <cuda_runtime.h>
#include <math.h>

#define NU 50000
#define NI 100000
#define NE 200000
#define NREL 32
#define DIM 64
#define NB 4096
#define EKG 2000000
#define EUI_HALF 1000000
#define NNODES 150000      // NU + NI

#define MAXLE NI           // upper bound on live entities (each item maps to one entity)
#define MAXLN (3 * NB)     // upper bound on live node rows = 12288

#define GEMM_BLOCKS ((NE + 255) / 256)          // 782
#define ZF4_AGGC  (MAXLE * DIM / 4)             // 1,600,000
#define ZF4_AGG2C (MAXLN * DIM / 4)             // 196,608
#define ZF4_TOTC  (ZF4_AGGC + ZF4_AGG2C)        // 1,796,608
#define CZBLOCKS  ((ZF4_TOTC + 2047) / 2048)    // 878

#define CKG_BLOCKS ((EKG + 255) / 256)          // 7813
#define CUI_BLOCKS ((EUI_HALF + 255) / 256)     // 3907
#define INIT_BLOCKS (GEMM_BLOCKS + CZBLOCKS + CKG_BLOCKS + 2 * CUI_BLOCKS)

#define EA_KG_BLOCKS 2048
#define EA_UI_BLOCKS 256
#define EB_BLOCKS 512

#define NFLAG_WORK (NI + 3 * NB)                // 112,288
#define DEGZ_F4 (MAXLE / 4)                     // 25,000
#define SF_THREADS (NFLAG_WORK + DEGZ_F4)
#define SF_BLOCKS ((SF_THREADS + 255) / 256)

#define CLEAN_F4E (NE / 4)                      // 50,000
#define CLEAN_F4N (NNODES / 4)                  // 37,500
#define CLEAN_BLOCKS (((CLEAN_F4E > CLEAN_F4N ? CLEAN_F4E : CLEAN_F4N) + 255) / 256)

// ---------------- scratch (static device globals; no allocation) ----------------
__device__ float g_y[NE * DIM];             // entity_emb @ W^T
__device__ float g_aggC[MAXLE * DIM];       // KG segment sum (dense live-entity rows)
__device__ float g_degC[MAXLE];             // KG in-degree (dense)
__device__ float g_itemkg[NI * DIM];        // per-item post-processed KG embedding
__device__ float g_agg2C[MAXLN * DIM];      // UI segment sum (dense live-node rows)
__device__ float g_gate[NREL * DIM];        // sigmoid(relation_emb)
__device__ int g_remapE[NE];                // 0 = dead, >=2 -> dense id + 2 (zeroed by cleanup)
__device__ int g_remapN[NNODES];            // same for UI node rows
__device__ int g_nLiveE, g_nLiveN;
__device__ int g_nKG, g_nUIA, g_nUIB;       // compacted counts
__device__ int   g_ksrc[EKG], g_kdst[EKG], g_krel[EKG];
__device__ int   g_arow[EUI_HALF], g_acol[EUI_HALF];
__device__ float g_aval[EUI_HALF];
__device__ int   g_brow[EUI_HALF], g_bcol[EUI_HALF];
__device__ float g_bval[EUI_HALF];

// vectorized no-return global atomic add (sm_90+)
__device__ __forceinline__ void red_add_v4(float* addr, float x, float y, float z, float w) {
    asm volatile("red.global.add.v4.f32 [%0], {%1,%2,%3,%4};"
                 :: "l"(addr), "f"(x), "f"(y), "f"(z), "f"(w)
                 : "memory");
}

__device__ __forceinline__ unsigned long long pack2(float a, float b) {
    unsigned long long r;
    asm("mov.b64 %0, {%1, %2};" : "=l"(r) : "f"(a), "f"(b));
    return r;
}
__device__ __forceinline__ void unpack2(unsigned long long v, float& a, float& b) {
    asm("mov.b64 {%0, %1}, %2;" : "=f"(a), "=f"(b) : "l"(v));
}
__device__ __forceinline__ void fma2(unsigned long long& d, unsigned long long a,
                                     unsigned long long b) {
    asm("fma.rn.f32x2 %0, %1, %2, %3;" : "=l"(d) : "l"(a), "l"(b), "l"(d));
}

// ---------------- K1: claim dense ids for live entities/nodes + zero degC ----------------
__global__ void set_flags_kernel(const int* __restrict__ i2e,
                                 const int* __restrict__ qu,
                                 const int* __restrict__ qi,
                                 const int* __restrict__ qn) {
    int t = blockIdx.x * blockDim.x + threadIdx.x;
    if (t < NI) {
        int e = __ldg(i2e + t);
        if (atomicCAS(&g_remapE[e], 0, 1) == 0)
            g_remapE[e] = 2 + atomicAdd(&g_nLiveE, 1);
    } else if (t < NFLAG_WORK) {
        int r = t - NI;
        int node;
        if (r < NB) node = __ldg(qu + r);
        else if (r < 2 * NB) node = NU + __ldg(qi + r - NB);
        else node = NU + __ldg(qn + r - 2 * NB);
        if (atomicCAS(&g_remapN[node], 0, 1) == 0)
            g_remapN[node] = 2 + atomicAdd(&g_nLiveN, 1);
    } else {
        int z = t - NFLAG_WORK;
        if (z < DEGZ_F4)
            reinterpret_cast<float4*>(g_degC)[z] = make_float4(0.f, 0.f, 0.f, 0.f);
    }
}

// ---------------- K2: fused GEMM + zero(dense aggs) + edge compaction + deg ----------------
__global__ void init_kernel(const float* __restrict__ x, const float* __restrict__ W,
                            const float* __restrict__ rel_emb,
                            const int* __restrict__ ksrc, const int* __restrict__ kdst,
                            const int* __restrict__ krel,
                            const int* __restrict__ urow, const int* __restrict__ ucol,
                            const float* __restrict__ uval) {
    int b = blockIdx.x;
    int tid = threadIdx.x;  // 256
    int lane = tid & 31;
    if (b < GEMM_BLOCKS) {
        __shared__ float sWt[DIM][DIM];   // sWt[k][o] = W[o][k]
        for (int idx = tid; idx < DIM * DIM; idx += 256) {
            int o = idx >> 6, k = idx & 63;
            sWt[k][o] = W[idx];
        }
        __syncthreads();
        int row = b * 256 + tid;
        if (row >= NE) return;
        const float4* xp = reinterpret_cast<const float4*>(x + (size_t)row * DIM);
        unsigned long long acc[32];
#pragma unroll
        for (int m = 0; m < 32; m++) acc[m] = 0ull;
#pragma unroll 4
        for (int kc = 0; kc < 16; kc++) {
            float4 xq = __ldg(xp + kc);
#pragma unroll
            for (int j = 0; j < 4; j++) {
                float xv = (j == 0) ? xq.x : (j == 1) ? xq.y : (j == 2) ? xq.z : xq.w;
                unsigned long long xx = pack2(xv, xv);
                const float4* wrow = reinterpret_cast<const float4*>(sWt[kc * 4 + j]);
#pragma unroll
                for (int o4 = 0; o4 < 16; o4++) {
                    float4 w = wrow[o4];
                    fma2(acc[2 * o4],     xx, pack2(w.x, w.y));
                    fma2(acc[2 * o4 + 1], xx, pack2(w.z, w.w));
                }
            }
        }
        float4* yp = reinterpret_cast<float4*>(g_y + (size_t)row * DIM);
#pragma unroll
        for (int j = 0; j < 16; j++) {
            float a0, a1, b0, b1;
            unpack2(acc[2 * j], a0, a1);
            unpack2(acc[2 * j + 1], b0, b1);
            yp[j] = make_float4(a0, a1, b0, b1);
        }
        return;
    }
    b -= GEMM_BLOCKS;
    if (b < CZBLOCKS) {
        if (b == 0) {
            for (int i = tid; i < NREL * DIM; i += 256) {
                float v = rel_emb[i];
                g_gate[i] = 1.0f / (1.0f + __expf(-v));
            }
        }
        float4 z = make_float4(0.f, 0.f, 0.f, 0.f);
        int base = b * 2048 + tid;
#pragma unroll
        for (int j = 0; j < 8; j++) {
            int i = base + j * 256;
            if (i < ZF4_AGGC) {
                reinterpret_cast<float4*>(g_aggC)[i] = z;
            } else if (i < ZF4_TOTC) {
                reinterpret_cast<float4*>(g_agg2C)[i - ZF4_AGGC] = z;
            }
        }
        return;
    }
    b -= CZBLOCKS;
    if (b < CKG_BLOCKS) {
        // compact KG edges with live dst; dst stored REMAPPED; count deg here
        int e = b * 256 + tid;
        bool live = false;
        int s = 0, dr = 0, r = 0;
        if (e < EKG) {
            int d = __ldg(kdst + e);
            int m = g_remapE[d];
            live = (m >= 2);
            if (live) {
                dr = m - 2;
                s = __ldg(ksrc + e);
                r = __ldg(krel + e);
                atomicAdd(&g_degC[dr], 1.0f);
            }
        }
        unsigned m = __ballot_sync(0xffffffffu, live);
        if (!m) return;
        int leader = __ffs(m) - 1;
        int base = 0;
        if (lane == leader) base = atomicAdd(&g_nKG, __popc(m));
        base = __shfl_sync(0xffffffffu, base, leader);
        if (live) {
            int off = base + __popc(m & ((1u << lane) - 1u));
            g_ksrc[off] = s; g_kdst[off] = dr; g_krel[off] = r;
        }
        return;
    }
    b -= CKG_BLOCKS;
    {
        // compact UI edges with live row; row stored REMAPPED.
        // half 0: e in [0, EUI_HALF)           row=user, col=item  -> B list
        // half 1: e in [EUI_HALF, 2*EUI_HALF)  row=item, col=user  -> A list
        int half = (b < CUI_BLOCKS) ? 0 : 1;
        int bb = (half == 0) ? b : b - CUI_BLOCKS;
        int e = bb * 256 + tid + half * EUI_HALF;
        bool live = false;
        int rr = 0, cc = 0;
        float vv = 0.f;
        if (e < (half + 1) * EUI_HALF) {
            int row = __ldg(urow + e);
            int m = g_remapN[row];
            live = (m >= 2);
            if (live) { rr = m - 2; cc = __ldg(ucol + e); vv = __ldg(uval + e); }
        }
        unsigned m = __ballot_sync(0xffffffffu, live);
        if (!m) return;
        int leader = __ffs(m) - 1;
        int base = 0;
        if (lane == leader) base = atomicAdd(half ? &g_nUIA : &g_nUIB, __popc(m));
        base = __shfl_sync(0xffffffffu, base, leader);
        if (live) {
            int off = base + __popc(m & ((1u << lane) - 1u));
            if (half) { g_arow[off] = rr; g_acol[off] = cc; g_aval[off] = vv; }
            else      { g_brow[off] = rr; g_bcol[off] = cc; g_bval[off] = vv; }
        }
    }
}

// ---------------- K3: compacted KG edges + compacted UI user-gather edges ----------------
__global__ void edgeA_kernel(const float* __restrict__ user_emb) {
    int b = blockIdx.x;
    int tid = threadIdx.x;
    int q = tid & 7;
    if (b < EA_KG_BLOCKS) {
        int n = g_nKG;
        int slot = (b * 256 + tid) >> 3;
        for (; slot < n; slot += (EA_KG_BLOCKS * 256) / 8) {
            int s = g_ksrc[slot], dr = g_kdst[slot], r = g_krel[slot];
            const float4* yp = reinterpret_cast<const float4*>(g_y + (size_t)s * DIM) + q;
            const float4* gp = reinterpret_cast<const float4*>(g_gate + r * DIM) + q;
            float4 v0 = __ldg(yp);
            float4 v1 = __ldg(yp + 8);
            float4 g0 = __ldg(gp);
            float4 g1 = __ldg(gp + 8);
            float* ap = g_aggC + (size_t)dr * DIM + q * 4;
            red_add_v4(ap,      v0.x * g0.x, v0.y * g0.y, v0.z * g0.z, v0.w * g0.w);
            red_add_v4(ap + 32, v1.x * g1.x, v1.y * g1.y, v1.z * g1.z, v1.w * g1.w);
        }
    } else {
        int n = g_nUIA;
        int slot = ((b - EA_KG_BLOCKS) * 256 + tid) >> 3;
        for (; slot < n; slot += (EA_UI_BLOCKS * 256) / 8) {
            int rr = g_arow[slot], cc = g_acol[slot];
            float w = g_aval[slot];
            const float4* sp = reinterpret_cast<const float4*>(user_emb + (size_t)cc * DIM) + q;
            float4 v0 = __ldg(sp);
            float4 v1 = __ldg(sp + 8);
            float* ap = g_agg2C + (size_t)rr * DIM + q * 4;
            red_add_v4(ap,      w * v0.x, w * v0.y, w * v0.z, w * v0.w);
            red_add_v4(ap + 32, w * v1.x, w * v1.y, w * v1.z, w * v1.w);
        }
    }
}

// ---------------- K4: per-ITEM post (16 lanes/row, float4) ----------------
__global__ void item_post_kernel(const float* __restrict__ ent, const int* __restrict__ i2e) {
    int tid = threadIdx.x;
    int lane = tid & 31;
    int half = lane >> 4;
    int l16 = lane & 15;
    int item = blockIdx.x * 16 + (tid >> 5) * 2 + half;
    if (item >= NI) return;
    int e = __ldg(i2e + item);
    int re = g_remapE[e] - 2;       // guaranteed claimed
    float inv = 1.0f / fmaxf(g_degC[re], 1.0f);
    float4 a = *reinterpret_cast<const float4*>(&g_aggC[(size_t)re * DIM + l16 * 4]);
    float4 x0 = __ldg(reinterpret_cast<const float4*>(&ent[(size_t)e * DIM + l16 * 4]));
    float vx = fmaf(a.x, inv, x0.x);
    float vy = fmaf(a.y, inv, x0.y);
    float vz = fmaf(a.z, inv, x0.z);
    float vw = fmaf(a.w, inv, x0.w);
    vx = (vx > 0.f) ? vx : (__expf(vx) - 1.f);
    vy = (vy > 0.f) ? vy : (__expf(vy) - 1.f);
    vz = (vz > 0.f) ? vz : (__expf(vz) - 1.f);
    vw = (vw > 0.f) ? vw : (__expf(vw) - 1.f);
    float ss = vx * vx + vy * vy + vz * vz + vw * vw;
#pragma unroll
    for (int o = 8; o; o >>= 1) ss += __shfl_xor_sync(0xffffffffu, ss, o);
    float scale = 1.0f / fmaxf(sqrtf(ss), 1e-12f);
    float4 out = make_float4(vx * scale, vy * scale, vz * scale, vw * scale);
    *reinterpret_cast<float4*>(&g_itemkg[(size_t)item * DIM + l16 * 4]) = out;
}

// ---------------- K5: compacted UI item-gather edges ----------------
__global__ void edgeB_kernel() {
    int tid = threadIdx.x;
    int q = tid & 7;
    int n = g_nUIB;
    int slot = (blockIdx.x * 256 + tid) >> 3;
    for (; slot < n; slot += (EB_BLOCKS * 256) / 8) {
        int rr = g_brow[slot], cc = g_bcol[slot];
        float w = g_bval[slot];
        const float4* sp = reinterpret_cast<const float4*>(g_itemkg + (size_t)(cc - NU) * DIM) + q;
        float4 v0 = __ldg(sp);
        float4 v1 = __ldg(sp + 8);
        float* ap = g_agg2C + (size_t)rr * DIM + q * 4;
        red_add_v4(ap,      w * v0.x, w * v0.y, w * v0.z, w * v0.w);
        red_add_v4(ap + 32, w * v1.x, w * v1.y, w * v1.z, w * v1.w);
    }
}

// ---------------- K6: fused intent + queries (one warp per query) ----------------
__global__ void query_kernel(const int* __restrict__ qu, const int* __restrict__ qi,
                             const int* __restrict__ qn,
                             const float* __restrict__ user_emb,
                             const float* __restrict__ router_w,
                             const float* __restrict__ router_b,
                             const float* __restrict__ iw,
                             const float* __restrict__ rel_emb,
                             float* __restrict__ out) {
    __shared__ float s_intent[2 * DIM];
    __shared__ float s_sw[2][NREL];
    int tid = threadIdx.x;  // 256
    if (tid < 2) {
        float m = -1e30f;
#pragma unroll
        for (int k = 0; k < NREL; k++) m = fmaxf(m, __ldg(iw + tid * NREL + k));
        float s = 0.f;
#pragma unroll
        for (int k = 0; k < NREL; k++) {
            float e = __expf(__ldg(iw + tid * NREL + k) - m);
            s_sw[tid][k] = e; s += e;
        }
        float inv = 1.0f / s;
#pragma unroll
        for (int k = 0; k < NREL; k++) s_sw[tid][k] *= inv;
    }
    __syncthreads();
    if (tid < 64) {
#pragma unroll
        for (int intent = 0; intent < 2; intent++) {
            float acc = 0.f;
#pragma unroll
            for (int k = 0; k < NREL; k++) acc += s_sw[intent][k] * __ldg(rel_emb + k * DIM + tid);
            s_intent[intent * DIM + tid] = acc;
        }
    }
    __syncthreads();

    int warp = (blockIdx.x * blockDim.x + tid) >> 5;
    int lane = tid & 31;
    if (warp >= NB) return;
    int uu = __ldg(qu + warp), pi = __ldg(qi + warp), ni = __ldg(qn + warp);
    int ru = g_remapN[uu] - 2;
    int rp = g_remapN[NU + pi] - 2;
    int rn = g_remapN[NU + ni] - 2;

    float2 ue0 = __ldg(reinterpret_cast<const float2*>(&user_emb[(size_t)uu * DIM + lane * 2]));
    float2 ag = *reinterpret_cast<const float2*>(&g_agg2C[(size_t)ru * DIM + lane * 2]);
    float fux = 0.5f * (ue0.x + ag.x);
    float fuy = 0.5f * (ue0.y + ag.y);

    float2 rw0 = __ldg(reinterpret_cast<const float2*>(&router_w[lane * 2]));
    float2 rw1 = __ldg(reinterpret_cast<const float2*>(&router_w[DIM + lane * 2]));
    float l0 = fux * rw0.x + fuy * rw0.y;
    float l1 = fux * rw1.x + fuy * rw1.y;
#pragma unroll
    for (int o = 16; o; o >>= 1) {
        l0 += __shfl_xor_sync(0xffffffffu, l0, o);
        l1 += __shfl_xor_sync(0xffffffffu, l1, o);
    }
    l0 += __ldg(router_b + 0);
    l1 += __ldg(router_b + 1);
    float m = fmaxf(l0, l1);
    float e0 = __expf(l0 - m), e1 = __expf(l1 - m);
    float inv = 1.0f / (e0 + e1);
    float p0 = e0 * inv, p1 = e1 * inv;

    float2 i0 = *reinterpret_cast<const float2*>(&s_intent[lane * 2]);
    float2 i1 = *reinterpret_cast<const float2*>(&s_intent[DIM + lane * 2]);
    float uex = fux + p0 * i0.x + p1 * i1.x;
    float uey = fuy + p0 * i0.y + p1 * i1.y;

    float2 ik = *reinterpret_cast<const float2*>(&g_itemkg[(size_t)pi * DIM + lane * 2]);
    float2 a2 = *reinterpret_cast<const float2*>(&g_agg2C[(size_t)rp * DIM + lane * 2]);
    float pos = uex * (1.5f * ik.x + 0.5f * a2.x) + uey * (1.5f * ik.y + 0.5f * a2.y);

    float2 nk = *reinterpret_cast<const float2*>(&g_itemkg[(size_t)ni * DIM + lane * 2]);
    float2 n2 = *reinterpret_cast<const float2*>(&g_agg2C[(size_t)rn * DIM + lane * 2]);
    float neg = uex * (1.5f * nk.x + 0.5f * n2.x) + uey * (1.5f * nk.y + 0.5f * n2.y);

#pragma unroll
    for (int o = 16; o; o >>= 1) {
        pos += __shfl_xor_sync(0xffffffffu, pos, o);
        neg += __shfl_xor_sync(0xffffffffu, neg, o);
    }
    if (lane == 0) {
        out[warp] = pos;
        out[NB + warp] = neg;
    }
}

// ---------------- K7: cleanup for next call (deterministic per-call state) ----------------
__global__ void cleanup_kernel() {
    int t = blockIdx.x * blockDim.x + threadIdx.x;
    if (t == 0) { g_nKG = 0; g_nUIA = 0; g_nUIB = 0; g_nLiveE = 0; g_nLiveN = 0; }
    int4 z = make_int4(0, 0, 0, 0);
    if (t < CLEAN_F4E) reinterpret_cast<int4*>(g_remapE)[t] = z;
    if (t < CLEAN_F4N) reinterpret_cast<int4*>(g_remapN)[t] = z;
}

// ---------------- launch ----------------
extern "C" void kernel_launch(void* const* d_in, const int* in_sizes, int n_in,
                              void* d_out, int out_size) {
    const int*   u          = (const int*)d_in[0];
    const int*   it         = (const int*)d_in[1];
    const int*   neg_i      = (const int*)d_in[2];
    const float* user_emb   = (const float*)d_in[3];
    const float* entity_emb = (const float*)d_in[4];
    const float* rel_emb    = (const float*)d_in[5];
    const float* intent_w   = (const float*)d_in[6];
    const float* router_w   = (const float*)d_in[7];
    const float* router_b   = (const float*)d_in[8];
    const float* kg_w       = (const float*)d_in[9];
    const float* ui_vals    = (const float*)d_in[10];
    const int*   item2ent   = (const int*)d_in[11];
    const int*   kg_src     = (const int*)d_in[12];
    const int*   kg_dst     = (const int*)d_in[13];
    const int*   kg_rel     = (const int*)d_in[14];
    const int*   ui_row     = (const int*)d_in[15];
    const int*   ui_col     = (const int*)d_in[16];
    float* out = (float*)d_out;

    set_flags_kernel<<<SF_BLOCKS, 256>>>(item2ent, u, it, neg_i);
    init_kernel<<<INIT_BLOCKS, 256>>>(entity_emb, kg_w, rel_emb,
                                      kg_src, kg_dst, kg_rel,
                                      ui_row, ui_col, ui_vals);
    edgeA_kernel<<<EA_KG_BLOCKS + EA_UI_BLOCKS, 256>>>(user_emb);
    item_post_kernel<<<(NI + 15) / 16, 256>>>(entity_emb, item2ent);
    edgeB_kernel<<<EB_BLOCKS, 256>>>();
    query_kernel<<<(NB * 32 + 255) / 256, 256>>>(u, it, neg_i, user_emb, router_w, router_b,
                                                 intent_w, rel_emb, out);
    cleanup_kernel<<<CLEAN_BLOCKS, 256>>>();
}